// round 3
// baseline (speedup 1.0000x reference)
#include <cuda_runtime.h>
#include <math.h>

#define BATCH   8
#define CDIM    512
#define HH      64
#define WWID    64
#define NHEADS  8
#define HD      64
#define SEQ     512
#define PLANE_ALL ((size_t)BATCH * CDIM * HH * WWID)   // 16,777,216 floats per q/k/v

#define SST   516   // score smem row stride (floats), 16B aligned, bank-friendly
#define QKST  68    // Q/K/V smem row stride (floats), 16B aligned

// ---------------------------------------------------------------------------
// Kernel A: depthwise 3x3 conv (lepe) on v, written directly into out in the
// final [b, row*64+col, c] layout. Initializes every output element.
// ---------------------------------------------------------------------------
__global__ __launch_bounds__(256)
void lepe_kernel(const float* __restrict__ v, const float* __restrict__ cw,
                 const float* __restrict__ cb, float* __restrict__ out) {
    extern __shared__ float sm[];
    float* vs = sm;               // [64 ch][3 rows][65] = 12480 floats
    float* ws = vs + 64 * 195;    // [64][9]
    float* bs = ws + 576;         // [64]

    int bx  = blockIdx.x;         // b*64 + row
    int b   = bx >> 6;
    int row = bx & 63;
    int c0  = blockIdx.y * 64;
    int t   = threadIdx.x;

    // load 3 input rows x 64 channels x 64 cols (zero pad rows out of range)
    for (int idx = t; idx < 64 * 3 * 64; idx += 256) {
        int c   = idx / 192;
        int rem = idx - c * 192;
        int r   = rem >> 6;
        int col = rem & 63;
        int gr  = row + r - 1;
        float val = 0.f;
        if (gr >= 0 && gr < HH)
            val = v[(((size_t)b * CDIM + c0 + c) * HH + gr) * WWID + col];
        vs[c * 195 + r * 65 + col] = val;
    }
    for (int idx = t; idx < 576; idx += 256) ws[idx] = cw[(size_t)c0 * 9 + idx];
    if (t < 64) bs[t] = cb[c0 + t];
    __syncthreads();

    int c   = t & 63;
    int cg  = t >> 6;   // 0..3
    float w0 = ws[c*9+0], w1 = ws[c*9+1], w2 = ws[c*9+2];
    float w3 = ws[c*9+3], w4 = ws[c*9+4], w5 = ws[c*9+5];
    float w6 = ws[c*9+6], w7 = ws[c*9+7], w8 = ws[c*9+8];
    float bias = bs[c];
    const float* base = &vs[c * 195];

    #pragma unroll
    for (int it = 0; it < 16; it++) {
        int col = it * 4 + cg;
        float l0 = (col > 0)  ? base[0*65 + col - 1] : 0.f;
        float l1 = (col > 0)  ? base[1*65 + col - 1] : 0.f;
        float l2 = (col > 0)  ? base[2*65 + col - 1] : 0.f;
        float m0 = base[0*65 + col];
        float m1 = base[1*65 + col];
        float m2 = base[2*65 + col];
        float r0 = (col < 63) ? base[0*65 + col + 1] : 0.f;
        float r1 = (col < 63) ? base[1*65 + col + 1] : 0.f;
        float r2 = (col < 63) ? base[2*65 + col + 1] : 0.f;
        float sum = bias;
        sum += l0*w0 + m0*w1 + r0*w2;
        sum += l1*w3 + m1*w4 + r1*w5;
        sum += l2*w6 + m2*w7 + r2*w8;
        out[((size_t)b * 4096 + row * 64 + col) * CDIM + c0 + c] = sum;
    }
}

// ---------------------------------------------------------------------------
// Kernel B: windowed attention with polar RPE + cosine activation.
// CTA = (unit = window*8+head, row-block of 64 queries). Full 64x512 score
// tile in smem; single pass per GEMM.
// ---------------------------------------------------------------------------
__global__ __launch_bounds__(256, 1)
void attn_kernel(const float* __restrict__ temp, const float* __restrict__ polar,
                 float* __restrict__ out) {
    extern __shared__ float sm[];
    float* Ssc  = sm;                   // 64 * 516
    float* Qs   = Ssc + 64 * SST;       // 64 * 68   (layout [d][i])
    float* Ks   = Qs + 64 * QKST;       // 64 * 68   (layout [d][j])
    float* phiA = Ks + 64 * QKST;       // 512
    float* rinv = phiA + SEQ;           // 64
    float* Vs   = Qs;                   // alias: [j][d] in phase 3

    int bid  = blockIdx.x;
    int rb   = bid & 7;          // query row block within window
    int unit = bid >> 3;         // 0..511
    int h    = unit & 7;
    int wwin = (unit >> 3) & 7;  // stripe index
    int b    = unit >> 6;

    const float* qb = temp + ((size_t)b * CDIM + h * HD) * (HH * WWID);
    const float* kb = qb + PLANE_ALL;
    const float* vb = qb + 2 * PLANE_ALL;
    int t = threadIdx.x;

    // phi for the whole window (512 tokens)
    for (int s = t; s < SEQ; s += 256) {
        int rp = s >> 3, cp = wwin * 8 + (s & 7);
        phiA[s] = polar[(((size_t)b * HH + rp) * WWID + cp) * 2 + 1];
    }
    // load Q block -> Qs[d][i]
    for (int idx = t; idx < 4096; idx += 256) {
        int i = idx & 63, d = idx >> 6;
        int sg = rb * 64 + i;
        int rp = sg >> 3, cp = wwin * 8 + (sg & 7);
        Qs[d * QKST + i] = qb[(size_t)d * 4096 + rp * 64 + cp];
    }
    __syncthreads();

    int ti = t >> 4, tj = t & 15;
    int i0 = ti * 4, j0 = tj * 4;

    float phq[4];
    #pragma unroll
    for (int ii = 0; ii < 4; ii++) phq[ii] = phiA[rb * 64 + i0 + ii];

    // ---- Phase 1: scores = scale*Q@K^T + rpe, into Ssc ----
    for (int jc = 0; jc < 8; jc++) {
        for (int idx = t; idx < 4096; idx += 256) {
            int j = idx & 63, d = idx >> 6;
            int sg = jc * 64 + j;
            int rp = sg >> 3, cp = wwin * 8 + (sg & 7);
            Ks[d * QKST + j] = kb[(size_t)d * 4096 + rp * 64 + cp];
        }
        __syncthreads();

        float acc[4][4];
        #pragma unroll
        for (int ii = 0; ii < 4; ii++)
            #pragma unroll
            for (int jj = 0; jj < 4; jj++) acc[ii][jj] = 0.f;

        #pragma unroll 8
        for (int kk = 0; kk < 64; kk++) {
            float4 q4 = *(const float4*)&Qs[kk * QKST + i0];
            float4 k4 = *(const float4*)&Ks[kk * QKST + j0];
            float qa[4] = {q4.x, q4.y, q4.z, q4.w};
            float ka[4] = {k4.x, k4.y, k4.z, k4.w};
            #pragma unroll
            for (int ii = 0; ii < 4; ii++)
                #pragma unroll
                for (int jj = 0; jj < 4; jj++)
                    acc[ii][jj] = fmaf(qa[ii], ka[jj], acc[ii][jj]);
        }

        float pk0 = phiA[jc * 64 + j0 + 0];
        float pk1 = phiA[jc * 64 + j0 + 1];
        float pk2 = phiA[jc * 64 + j0 + 2];
        float pk3 = phiA[jc * 64 + j0 + 3];
        #pragma unroll
        for (int ii = 0; ii < 4; ii++) {
            float4 o;
            o.x = 0.125f * acc[ii][0] + phq[ii] - pk0;
            o.y = 0.125f * acc[ii][1] + phq[ii] - pk1;
            o.z = 0.125f * acc[ii][2] + phq[ii] - pk2;
            o.w = 0.125f * acc[ii][3] + phq[ii] - pk3;
            *(float4*)&Ssc[(i0 + ii) * SST + jc * 64 + j0] = o;
        }
        __syncthreads();
    }

    // ---- L1 row sums -> rinv ----
    {
        int row = t >> 2, quad = t & 3;
        float s = 0.f;
        for (int j = quad; j < SEQ; j += 4) s += fabsf(Ssc[row * SST + j]);
        s += __shfl_xor_sync(0xffffffffu, s, 1);
        s += __shfl_xor_sync(0xffffffffu, s, 2);
        if (quad == 0) rinv[row] = 1.5707963267948966f / (s + 1e-8f);
    }
    __syncthreads();

    // ---- Phase 2: attn = 1 - cos(score * rinv), even Taylor in z = x^2 ----
    {
        const float K1 =  0.5f;
        const float K2 = -1.f / 24.f;
        const float K3 =  1.f / 720.f;
        const float K4 = -1.f / 40320.f;
        const float K5 =  1.f / 3628800.f;
        const float K6 = -1.f / 479001600.f;
        for (int idx = t; idx < 64 * 128; idx += 256) {
            int i  = idx >> 7;
            int j4 = (idx & 127) << 2;
            float ri = rinv[i];
            float4 v4 = *(float4*)&Ssc[i * SST + j4];
            float xs[4] = {v4.x, v4.y, v4.z, v4.w};
            #pragma unroll
            for (int e = 0; e < 4; e++) {
                float x = xs[e] * ri;
                float z = x * x;
                float p = fmaf(z, K6, K5);
                p = fmaf(z, p, K4);
                p = fmaf(z, p, K3);
                p = fmaf(z, p, K2);
                p = fmaf(z, p, K1);
                xs[e] = z * p;
            }
            v4.x = xs[0]; v4.y = xs[1]; v4.z = xs[2]; v4.w = xs[3];
            *(float4*)&Ssc[i * SST + j4] = v4;
        }
    }
    __syncthreads();

    // ---- Phase 3: out += attn @ V ----
    float acc[4][4];
    #pragma unroll
    for (int ii = 0; ii < 4; ii++)
        #pragma unroll
        for (int dd = 0; dd < 4; dd++) acc[ii][dd] = 0.f;

    for (int jc = 0; jc < 8; jc++) {
        for (int idx = t; idx < 4096; idx += 256) {
            int j = idx & 63, d = idx >> 6;
            int sg = jc * 64 + j;
            int rp = sg >> 3, cp = wwin * 8 + (sg & 7);
            Vs[j * QKST + d] = vb[(size_t)d * 4096 + rp * 64 + cp];
        }
        __syncthreads();

        #pragma unroll 8
        for (int j = 0; j < 64; j++) {
            float4 vv = *(const float4*)&Vs[j * QKST + j0];
            float va[4] = {vv.x, vv.y, vv.z, vv.w};
            float a0 = Ssc[(i0 + 0) * SST + jc * 64 + j];
            float a1 = Ssc[(i0 + 1) * SST + jc * 64 + j];
            float a2 = Ssc[(i0 + 2) * SST + jc * 64 + j];
            float aa3 = Ssc[(i0 + 3) * SST + jc * 64 + j];
            float ar[4] = {a0, a1, a2, aa3};
            #pragma unroll
            for (int ii = 0; ii < 4; ii++)
                #pragma unroll
                for (int dd = 0; dd < 4; dd++)
                    acc[ii][dd] = fmaf(ar[ii], va[dd], acc[ii][dd]);
        }
        __syncthreads();
    }

    // epilogue: out[b, rp*64+cp, h*64+d] += acc (lepe already written by kernel A)
    #pragma unroll
    for (int ii = 0; ii < 4; ii++) {
        int sg = rb * 64 + i0 + ii;
        int rp = sg >> 3, cp = wwin * 8 + (sg & 7);
        size_t o = ((size_t)b * 4096 + rp * 64 + cp) * CDIM + h * HD + j0;
        float4 cur = *(float4*)&out[o];
        cur.x += acc[ii][0];
        cur.y += acc[ii][1];
        cur.z += acc[ii][2];
        cur.w += acc[ii][3];
        *(float4*)&out[o] = cur;
    }
}

// ---------------------------------------------------------------------------
extern "C" void kernel_launch(void* const* d_in, const int* in_sizes, int n_in,
                              void* d_out, int out_size) {
    const float* temp  = (const float*)d_in[0];  // [3, 8, 512, 64, 64]
    const float* polar = (const float*)d_in[1];  // [8, 64, 64, 2]
    const float* cw    = (const float*)d_in[2];  // [512, 1, 3, 3]
    const float* cb    = (const float*)d_in[3];  // [512]
    float* out = (float*)d_out;                  // [8, 4096, 512]

    const float* v = temp + 2 * PLANE_ALL;

    size_t smA = (size_t)(64 * 195 + 576 + 64) * sizeof(float);              // ~52.5 KB
    size_t smB = (size_t)(64 * SST + 2 * 64 * QKST + SEQ + 64) * sizeof(float); // ~169 KB
    cudaFuncSetAttribute(lepe_kernel, cudaFuncAttributeMaxDynamicSharedMemorySize, (int)smA);
    cudaFuncSetAttribute(attn_kernel, cudaFuncAttributeMaxDynamicSharedMemorySize, (int)smB);

    dim3 gA(BATCH * HH, CDIM / 64);
    lepe_kernel<<<gA, 256, smA>>>(v, cw, cb, out);
    attn_kernel<<<4096, 256, smB>>>(temp, polar, out);
}

// round 5
// speedup vs baseline: 1.2841x; 1.2841x over previous
#include <cuda_runtime.h>
#include <cuda_bf16.h>
#include <stdint.h>
#include <math.h>

#define BATCH   8
#define CDIM    512
#define HD      64
#define PLANE_ALL ((size_t)BATCH * CDIM * 64 * 64)

// smem byte offsets (attn kernel)
#define OFF_S    0                      /* 64 x 516 f32 = 132096 */
#define OFF_QH   132096                 /* each bf16 buf: 64 x 72 x 2 = 9216 */
#define OFF_QL   141312
#define OFF_KH   150528                 /* reused as VT-high in phase 2 */
#define OFF_KL   159744                 /* reused as VT-low  */
#define OFF_PH   168960
#define OFF_PL   178176
#define OFF_PHI  187392                 /* 512 f32 */
#define OFF_RI   189440                 /* 64 f32 */
#define SMEM_ATTN 189696

#define SST 516
#define BST 72   /* bf16 row stride for all operand buffers */

__device__ __forceinline__ void split1(float x, __nv_bfloat16& h, __nv_bfloat16& l) {
    h = __float2bfloat16(x);
    l = __float2bfloat16(x - __bfloat162float(h));
}

__device__ __forceinline__ void mma16816(float* c, uint32_t a0, uint32_t a1,
                                         uint32_t a2, uint32_t a3,
                                         uint32_t b0, uint32_t b1) {
    asm volatile(
        "mma.sync.aligned.m16n8k16.row.col.f32.bf16.bf16.f32 "
        "{%0,%1,%2,%3}, {%4,%5,%6,%7}, {%8,%9}, {%0,%1,%2,%3};"
        : "+f"(c[0]), "+f"(c[1]), "+f"(c[2]), "+f"(c[3])
        : "r"(a0), "r"(a1), "r"(a2), "r"(a3), "r"(b0), "r"(b1));
}

// ---------------------------------------------------------------------------
// Kernel A: depthwise 3x3 conv (lepe) -> writes base output layer
// ---------------------------------------------------------------------------
__global__ __launch_bounds__(256)
void lepe_kernel(const float* __restrict__ v, const float* __restrict__ cw,
                 const float* __restrict__ cb, float* __restrict__ out) {
    extern __shared__ float sm[];
    float* vs = sm;               // [64 ch][3 rows][65]
    float* ws = vs + 64 * 195;    // [64][9]
    float* bs = ws + 576;         // [64]

    int bx  = blockIdx.x;
    int b   = bx >> 6;
    int row = bx & 63;
    int c0  = blockIdx.y * 64;
    int t   = threadIdx.x;

    for (int idx = t; idx < 64 * 3 * 64; idx += 256) {
        int c = idx / 192, rem = idx - c * 192;
        int r = rem >> 6, col = rem & 63;
        int gr = row + r - 1;
        float val = 0.f;
        if (gr >= 0 && gr < 64)
            val = v[(((size_t)b * CDIM + c0 + c) * 64 + gr) * 64 + col];
        vs[c * 195 + r * 65 + col] = val;
    }
    for (int idx = t; idx < 576; idx += 256) ws[idx] = cw[(size_t)c0 * 9 + idx];
    if (t < 64) bs[t] = cb[c0 + t];
    __syncthreads();

    int c = t & 63, cg = t >> 6;
    float w0 = ws[c*9+0], w1 = ws[c*9+1], w2 = ws[c*9+2];
    float w3 = ws[c*9+3], w4 = ws[c*9+4], w5 = ws[c*9+5];
    float w6 = ws[c*9+6], w7 = ws[c*9+7], w8 = ws[c*9+8];
    float bias = bs[c];
    const float* base = &vs[c * 195];

    #pragma unroll
    for (int it = 0; it < 16; it++) {
        int col = it * 4 + cg;
        float l0 = (col > 0)  ? base[0*65 + col - 1] : 0.f;
        float l1 = (col > 0)  ? base[1*65 + col - 1] : 0.f;
        float l2 = (col > 0)  ? base[2*65 + col - 1] : 0.f;
        float m0 = base[0*65 + col], m1 = base[1*65 + col], m2 = base[2*65 + col];
        float r0 = (col < 63) ? base[0*65 + col + 1] : 0.f;
        float r1 = (col < 63) ? base[1*65 + col + 1] : 0.f;
        float r2 = (col < 63) ? base[2*65 + col + 1] : 0.f;
        float sum = bias;
        sum += l0*w0 + m0*w1 + r0*w2;
        sum += l1*w3 + m1*w4 + r1*w5;
        sum += l2*w6 + m2*w7 + r2*w8;
        out[((size_t)b * 4096 + row * 64 + col) * CDIM + c0 + c] = sum;
    }
}

// ---------------------------------------------------------------------------
// Kernel B: attention via warp-level bf16 mma.sync with 3-term split.
// CTA = (unit, 64-query block). grid 4096, 256 threads (8 warps).
// ---------------------------------------------------------------------------
__global__ __launch_bounds__(256, 1)
void attn_mma_kernel(const float* __restrict__ temp, const float* __restrict__ polar,
                     float* __restrict__ out) {
    extern __shared__ char smc[];
    float* S = (float*)(smc + OFF_S);
    __nv_bfloat16* QH = (__nv_bfloat16*)(smc + OFF_QH);
    __nv_bfloat16* QL = (__nv_bfloat16*)(smc + OFF_QL);
    __nv_bfloat16* KH = (__nv_bfloat16*)(smc + OFF_KH);  // VT-high in phase 2
    __nv_bfloat16* KL = (__nv_bfloat16*)(smc + OFF_KL);  // VT-low
    __nv_bfloat16* PH = (__nv_bfloat16*)(smc + OFF_PH);
    __nv_bfloat16* PL = (__nv_bfloat16*)(smc + OFF_PL);
    float* phiA = (float*)(smc + OFF_PHI);
    float* riA  = (float*)(smc + OFF_RI);

    int t = threadIdx.x;
    int bid = blockIdx.x;
    int rb = bid & 7;
    int unit = bid >> 3;
    int h = unit & 7, ww = (unit >> 3) & 7, b = unit >> 6;

    const float* qb = temp + ((size_t)b * CDIM + h * HD) * 4096;
    const float* kb = qb + PLANE_ALL;
    const float* vb = qb + 2 * PLANE_ALL;

    int lane = t & 31, wid = t >> 5;
    int g = lane >> 2, tg = lane & 3;
    int m0 = (wid >> 1) * 16;          // warp m-tile base row
    int nb = (wid & 1) * 32;           // warp n base within 64-chunk

    // phi for the window
    for (int s = t; s < 512; s += 256) {
        int rp = s >> 3, cp = ww * 8 + (s & 7);
        phiA[s] = polar[(((size_t)b * 64 + rp) * 64 + cp) * 2 + 1];
    }
    // Q convert (scale folded): [i][d] bf16 hi/lo
    for (int idx = t; idx < 4096; idx += 256) {
        int i = idx & 63, d = idx >> 6;
        int sg = rb * 64 + i;
        int sp = (sg >> 3) * 64 + ww * 8 + (sg & 7);
        float x = 0.125f * qb[(size_t)d * 4096 + sp];
        __nv_bfloat16 xh, xl; split1(x, xh, xl);
        QH[i * BST + d] = xh; QL[i * BST + d] = xl;
    }

    // ---- Phase 1: S = Qs @ K^T, streamed in 64-col chunks ----
    for (int jc = 0; jc < 8; jc++) {
        for (int idx = t; idx < 4096; idx += 256) {
            int j = idx & 63, d = idx >> 6;
            int sg = jc * 64 + j;
            int sp = (sg >> 3) * 64 + ww * 8 + (sg & 7);
            float x = kb[(size_t)d * 4096 + sp];
            __nv_bfloat16 xh, xl; split1(x, xh, xl);
            KH[j * BST + d] = xh; KL[j * BST + d] = xl;
        }
        __syncthreads();

        float acc[4][4];
        #pragma unroll
        for (int nt = 0; nt < 4; nt++)
            #pragma unroll
            for (int e = 0; e < 4; e++) acc[nt][e] = 0.f;

        #pragma unroll
        for (int term = 0; term < 3; term++) {
            const __nv_bfloat16* A = (term == 2) ? QL : QH;
            const __nv_bfloat16* B = (term == 1) ? KL : KH;
            #pragma unroll
            for (int kt = 0; kt < 4; kt++) {
                int k0 = kt * 16 + tg * 2;
                uint32_t a0 = *(const uint32_t*)&A[(m0 + g)     * BST + k0];
                uint32_t a1 = *(const uint32_t*)&A[(m0 + g + 8) * BST + k0];
                uint32_t a2 = *(const uint32_t*)&A[(m0 + g)     * BST + k0 + 8];
                uint32_t a3 = *(const uint32_t*)&A[(m0 + g + 8) * BST + k0 + 8];
                #pragma unroll
                for (int nt = 0; nt < 4; nt++) {
                    int n = nb + nt * 8 + g;
                    uint32_t b0 = *(const uint32_t*)&B[n * BST + k0];
                    uint32_t b1 = *(const uint32_t*)&B[n * BST + k0 + 8];
                    mma16816(acc[nt], a0, a1, a2, a3, b0, b1);
                }
            }
        }
        #pragma unroll
        for (int nt = 0; nt < 4; nt++) {
            int col = jc * 64 + nb + nt * 8 + tg * 2;
            *(float2*)&S[(m0 + g)     * SST + col] = make_float2(acc[nt][0], acc[nt][1]);
            *(float2*)&S[(m0 + g + 8) * SST + col] = make_float2(acc[nt][2], acc[nt][3]);
        }
        __syncthreads();
    }

    // ---- L1 row sums (with RPE) ----
    {
        int row = t >> 2, quad = t & 3;
        float phq = phiA[rb * 64 + row];
        float ssum = 0.f;
        for (int j4 = quad * 4; j4 < 512; j4 += 16) {
            float4 v = *(float4*)&S[row * SST + j4];
            float4 p = *(const float4*)&phiA[j4];
            ssum += fabsf(v.x + phq - p.x) + fabsf(v.y + phq - p.y)
                  + fabsf(v.z + phq - p.z) + fabsf(v.w + phq - p.w);
        }
        ssum += __shfl_xor_sync(0xffffffffu, ssum, 1);
        ssum += __shfl_xor_sync(0xffffffffu, ssum, 2);
        if (quad == 0) riA[row] = 1.5707963267948966f / (ssum + 1e-8f);
    }
    __syncthreads();

    // ---- Phase 2: per chunk: convert V^T, activate P, P @ V accumulate ----
    const float K1 =  0.5f;
    const float K2 = -1.f / 24.f;
    const float K3 =  1.f / 720.f;
    const float K4 = -1.f / 40320.f;
    const float K5 =  1.f / 3628800.f;
    const float K6 = -1.f / 479001600.f;

    float oacc[4][4];
    #pragma unroll
    for (int nt = 0; nt < 4; nt++)
        #pragma unroll
        for (int e = 0; e < 4; e++) oacc[nt][e] = 0.f;

    int prow = t >> 2, pc0 = (t & 3) * 16;
    float my_ri = riA[prow];
    float my_pq = phiA[rb * 64 + prow];

    for (int jc = 0; jc < 8; jc++) {
        // V^T chunk: VT[d][j] = V[j][d]
        for (int idx = t; idx < 4096; idx += 256) {
            int j = idx & 63, d = idx >> 6;
            int sg = jc * 64 + j;
            int sp = (sg >> 3) * 64 + ww * 8 + (sg & 7);
            float x = vb[(size_t)d * 4096 + sp];
            __nv_bfloat16 xh, xl; split1(x, xh, xl);
            KH[d * BST + j] = xh; KL[d * BST + j] = xl;
        }
        // activate P chunk: thread owns row prow, cols pc0..pc0+15
        #pragma unroll
        for (int qq = 0; qq < 4; qq++) {
            int j0 = pc0 + qq * 4;
            float4 v = *(float4*)&S[prow * SST + jc * 64 + j0];
            float4 pk = *(const float4*)&phiA[jc * 64 + j0];
            float xs[4] = {v.x + my_pq - pk.x, v.y + my_pq - pk.y,
                           v.z + my_pq - pk.z, v.w + my_pq - pk.w};
            #pragma unroll
            for (int e = 0; e < 4; e++) {
                float x = xs[e] * my_ri;
                float z = x * x;
                float p = fmaf(z, K6, K5);
                p = fmaf(z, p, K4);
                p = fmaf(z, p, K3);
                p = fmaf(z, p, K2);
                p = fmaf(z, p, K1);
                xs[e] = z * p;
            }
            #pragma unroll
            for (int e = 0; e < 4; e++) {
                __nv_bfloat16 xh, xl; split1(xs[e], xh, xl);
                PH[prow * BST + j0 + e] = xh;
                PL[prow * BST + j0 + e] = xl;
            }
        }
        __syncthreads();

        #pragma unroll
        for (int term = 0; term < 3; term++) {
            const __nv_bfloat16* A = (term == 2) ? PL : PH;
            const __nv_bfloat16* B = (term == 1) ? KL : KH;   // VT buffers
            #pragma unroll
            for (int kt = 0; kt < 4; kt++) {
                int k0 = kt * 16 + tg * 2;
                uint32_t a0 = *(const uint32_t*)&A[(m0 + g)     * BST + k0];
                uint32_t a1 = *(const uint32_t*)&A[(m0 + g + 8) * BST + k0];
                uint32_t a2 = *(const uint32_t*)&A[(m0 + g)     * BST + k0 + 8];
                uint32_t a3 = *(const uint32_t*)&A[(m0 + g + 8) * BST + k0 + 8];
                #pragma unroll
                for (int nt = 0; nt < 4; nt++) {
                    int n = nb + nt * 8 + g;
                    uint32_t b0 = *(const uint32_t*)&B[n * BST + k0];
                    uint32_t b1 = *(const uint32_t*)&B[n * BST + k0 + 8];
                    mma16816(oacc[nt], a0, a1, a2, a3, b0, b1);
                }
            }
        }
        __syncthreads();
    }

    // ---- Epilogue: RMW into out (lepe base already written) ----
    {
        int sg0 = rb * 64 + m0 + g;
        int sg1 = sg0 + 8;
        int sp0 = (sg0 >> 3) * 64 + ww * 8 + (sg0 & 7);
        int sp1 = (sg1 >> 3) * 64 + ww * 8 + (sg1 & 7);
        float* o0 = out + ((size_t)b * 4096 + sp0) * CDIM + h * HD;
        float* o1 = out + ((size_t)b * 4096 + sp1) * CDIM + h * HD;
        #pragma unroll
        for (int nt = 0; nt < 4; nt++) {
            int d0 = nb + nt * 8 + tg * 2;
            float2 c0 = *(float2*)&o0[d0];
            c0.x += oacc[nt][0]; c0.y += oacc[nt][1];
            *(float2*)&o0[d0] = c0;
            float2 c1 = *(float2*)&o1[d0];
            c1.x += oacc[nt][2]; c1.y += oacc[nt][3];
            *(float2*)&o1[d0] = c1;
        }
    }
}

// ---------------------------------------------------------------------------
extern "C" void kernel_launch(void* const* d_in, const int* in_sizes, int n_in,
                              void* d_out, int out_size) {
    const float* temp  = (const float*)d_in[0];  // [3, 8, 512, 64, 64]
    const float* polar = (const float*)d_in[1];  // [8, 64, 64, 2]
    const float* cw    = (const float*)d_in[2];  // [512, 1, 3, 3]
    const float* cb    = (const float*)d_in[3];  // [512]
    float* out = (float*)d_out;                  // [8, 4096, 512]

    const float* v = temp + 2 * PLANE_ALL;

    size_t smA = (size_t)(64 * 195 + 576 + 64) * sizeof(float);
    cudaFuncSetAttribute(lepe_kernel, cudaFuncAttributeMaxDynamicSharedMemorySize, (int)smA);
    cudaFuncSetAttribute(attn_mma_kernel, cudaFuncAttributeMaxDynamicSharedMemorySize, SMEM_ATTN);

    dim3 gA(BATCH * 64, CDIM / 64);
    lepe_kernel<<<gA, 256, smA>>>(v, cw, cb, out);
    attn_mma_kernel<<<4096, 256, SMEM_ATTN>>>(temp, polar, out);
}

// round 8
// speedup vs baseline: 2.2496x; 1.7518x over previous
#include <cuda_runtime.h>
#include <cuda_bf16.h>
#include <stdint.h>
#include <math.h>

#define BATCH   8
#define CDIM    512
#define HD      64
#define UNITS   512
#define PLANE_ALL ((size_t)BATCH * CDIM * 64 * 64)

// ---- bf16 hi/lo scratch in operand layouts ----
// Q/K: [unit][token 512][d 64]  (128B rows)   V: [unit][d 64][j 512]
__device__ __nv_bfloat16 g_qh[(size_t)UNITS * 32768];
__device__ __nv_bfloat16 g_ql[(size_t)UNITS * 32768];
__device__ __nv_bfloat16 g_kh[(size_t)UNITS * 32768];
__device__ __nv_bfloat16 g_kl[(size_t)UNITS * 32768];
__device__ __nv_bfloat16 g_vh[(size_t)UNITS * 32768];
__device__ __nv_bfloat16 g_vl[(size_t)UNITS * 32768];

// ---- attn smem byte offsets ----
#define OFF_S    0          /* 64 x 516 f32 = 132096 */
#define OFF_QH   132096
#define OFF_QL   141312
#define OFF_K0H  150528     /* double-buffered K/V chunk: pair stride 18432 */
#define OFF_PH   187392
#define OFF_PL   196608
#define OFF_PHI  205824
#define OFF_RI   207872
#define SMEM_ATTN 208128

#define SST 516
#define BST 72      /* bf16 row stride (halves): frag loads conflict-free */

__device__ __forceinline__ void split1(float x, __nv_bfloat16& h, __nv_bfloat16& l) {
    h = __float2bfloat16(x);
    l = __float2bfloat16(x - __bfloat162float(h));
}
__device__ __forceinline__ uint32_t packbf(__nv_bfloat16 a, __nv_bfloat16 c) {
    return (uint32_t)__bfloat16_as_ushort(a) | ((uint32_t)__bfloat16_as_ushort(c) << 16);
}
__device__ __forceinline__ uint32_t smem_u32(const void* p) {
    uint32_t a;
    asm("{ .reg .u64 t; cvta.to.shared.u64 t, %1; cvt.u32.u64 %0, t; }" : "=r"(a) : "l"(p));
    return a;
}
__device__ __forceinline__ void mma16816(float* c, uint32_t a0, uint32_t a1,
                                         uint32_t a2, uint32_t a3,
                                         uint32_t b0, uint32_t b1) {
    asm volatile(
        "mma.sync.aligned.m16n8k16.row.col.f32.bf16.bf16.f32 "
        "{%0,%1,%2,%3}, {%4,%5,%6,%7}, {%8,%9}, {%0,%1,%2,%3};"
        : "+f"(c[0]), "+f"(c[1]), "+f"(c[2]), "+f"(c[3])
        : "r"(a0), "r"(a1), "r"(a2), "r"(a3), "r"(b0), "r"(b1));
}
#define CP16(d, s)  asm volatile("cp.async.cg.shared.global [%0], [%1], 16;" :: "r"(d), "l"(s))
#define CPCOMMIT()  asm volatile("cp.async.commit_group;" ::: "memory")
#define CPWAIT1()   asm volatile("cp.async.wait_group 1;" ::: "memory")
#define CPWAIT0()   asm volatile("cp.async.wait_group 0;" ::: "memory")

// ---------------------------------------------------------------------------
// Pre-pass 1: Q (scaled) and K -> bf16 hi/lo scratch [unit][token][d]
// block = (unit, chunk, tensor). Conflict-free smem transpose.
// ---------------------------------------------------------------------------
__global__ __launch_bounds__(256)
void prep_qk(const float* __restrict__ temp) {
    __shared__ __nv_bfloat16 sh[64 * BST];
    __shared__ __nv_bfloat16 sl[64 * BST];
    int bid = blockIdx.x;
    int tsel = bid & 1, jc = (bid >> 1) & 7, unit = bid >> 4;
    int h = unit & 7, ww = (unit >> 3) & 7, b = unit >> 6;
    const float* src = temp + (size_t)tsel * PLANE_ALL + ((size_t)b * CDIM + h * HD) * 4096;
    float scale = tsel ? 1.f : 0.125f;

    int t = threadIdx.x, lane = t & 31, w = t >> 5;
    int j = w * 8 + (lane & 7);
    int jg = jc * 64 + j;
    int sp = (jg >> 3) * 64 + ww * 8 + (jg & 7);
    const float* col = src + sp;

    #pragma unroll
    for (int it = 0; it < 8; it++) {
        int d = (it * 4 + (lane >> 3)) * 2;
        float a = scale * col[(size_t)d * 4096];
        float c = scale * col[(size_t)(d + 1) * 4096];
        __nv_bfloat16 ah, al, ch, cl;
        split1(a, ah, al); split1(c, ch, cl);
        *(uint32_t*)((char*)sh + j * 144 + d * 2) = packbf(ah, ch);
        *(uint32_t*)((char*)sl + j * 144 + d * 2) = packbf(al, cl);
    }
    __syncthreads();

    __nv_bfloat16* dh = (tsel ? g_kh : g_qh) + (size_t)unit * 32768 + jc * 4096;
    __nv_bfloat16* dl = (tsel ? g_kl : g_ql) + (size_t)unit * 32768 + jc * 4096;
    int seg = lane & 7, r4 = lane >> 3;
    #pragma unroll
    for (int it = 0; it < 2; it++) {
        int r = w * 8 + it * 4 + r4;
        *(uint4*)((char*)(dh + r * 64) + seg * 16) = *(uint4*)((char*)sh + r * 144 + seg * 16);
        *(uint4*)((char*)(dl + r * 64) + seg * 16) = *(uint4*)((char*)sl + r * 144 + seg * 16);
    }
}

// ---------------------------------------------------------------------------
// Pre-pass 2: V -> bf16 hi/lo scratch [unit][d][j]  (pure streaming)
// block = (unit, d-quad of 16)
// ---------------------------------------------------------------------------
__global__ __launch_bounds__(256)
void prep_v(const float* __restrict__ temp) {
    int bid = blockIdx.x;
    int unit = bid >> 2, d0 = (bid & 3) * 16;
    int h = unit & 7, ww = (unit >> 3) & 7, b = unit >> 6;
    const float* vb = temp + 2 * PLANE_ALL + ((size_t)b * CDIM + h * HD) * 4096;
    int t = threadIdx.x;
    #pragma unroll
    for (int it = 0; it < 16; it++) {
        int pid = it * 256 + t;
        int j = (pid & 255) * 2;
        int d = d0 + (pid >> 8);
        int sp = (j >> 3) * 64 + ww * 8 + (j & 7);
        float2 x = *(const float2*)&vb[(size_t)d * 4096 + sp];
        __nv_bfloat16 ah, al, ch, cl;
        split1(x.x, ah, al); split1(x.y, ch, cl);
        size_t o = (size_t)unit * 32768 + d * 512 + j;
        *(uint32_t*)&g_vh[o] = packbf(ah, ch);
        *(uint32_t*)&g_vl[o] = packbf(al, cl);
    }
}

// ---------------------------------------------------------------------------
// Kernel A: depthwise 3x3 conv (lepe) -> writes base output layer
// ---------------------------------------------------------------------------
__global__ __launch_bounds__(256)
void lepe_kernel(const float* __restrict__ v, const float* __restrict__ cw,
                 const float* __restrict__ cb, float* __restrict__ out) {
    extern __shared__ float sm[];
    float* vs = sm;
    float* ws = vs + 64 * 195;
    float* bs = ws + 576;

    int bx = blockIdx.x;
    int b = bx >> 6, row = bx & 63;
    int c0 = blockIdx.y * 64;
    int t = threadIdx.x;

    for (int idx = t; idx < 64 * 3 * 64; idx += 256) {
        int c = idx / 192, rem = idx - c * 192;
        int r = rem >> 6, col = rem & 63;
        int gr = row + r - 1;
        float val = 0.f;
        if (gr >= 0 && gr < 64)
            val = v[(((size_t)b * CDIM + c0 + c) * 64 + gr) * 64 + col];
        vs[c * 195 + r * 65 + col] = val;
    }
    for (int idx = t; idx < 576; idx += 256) ws[idx] = cw[(size_t)c0 * 9 + idx];
    if (t < 64) bs[t] = cb[c0 + t];
    __syncthreads();

    int c = t & 63, cg = t >> 6;
    float w0 = ws[c*9+0], w1 = ws[c*9+1], w2 = ws[c*9+2];
    float w3 = ws[c*9+3], w4 = ws[c*9+4], w5 = ws[c*9+5];
    float w6 = ws[c*9+6], w7 = ws[c*9+7], w8 = ws[c*9+8];
    float bias = bs[c];
    const float* base = &vs[c * 195];

    #pragma unroll
    for (int it = 0; it < 16; it++) {
        int col = it * 4 + cg;
        float l0 = (col > 0)  ? base[0*65 + col - 1] : 0.f;
        float l1 = (col > 0)  ? base[1*65 + col - 1] : 0.f;
        float l2 = (col > 0)  ? base[2*65 + col - 1] : 0.f;
        float m0 = base[0*65 + col], m1 = base[1*65 + col], m2 = base[2*65 + col];
        float r0 = (col < 63) ? base[0*65 + col + 1] : 0.f;
        float r1 = (col < 63) ? base[1*65 + col + 1] : 0.f;
        float r2 = (col < 63) ? base[2*65 + col + 1] : 0.f;
        float sum = bias;
        sum += l0*w0 + m0*w1 + r0*w2;
        sum += l1*w3 + m1*w4 + r1*w5;
        sum += l2*w6 + m2*w7 + r2*w8;
        out[((size_t)b * 4096 + row * 64 + col) * CDIM + c0 + c] = sum;
    }
}

// ---------------------------------------------------------------------------
// Kernel B: attention, mma.sync bf16 3-term split, cp.async double-buffered.
// CTA = (unit, 64-query block). grid 4096, 256 threads.
// ---------------------------------------------------------------------------
__global__ __launch_bounds__(256, 1)
void attn_mma_kernel(const float* __restrict__ polar, float* __restrict__ out) {
    extern __shared__ char smc[];
    const uint32_t sb = smem_u32(smc);
    float* S = (float*)(smc + OFF_S);
    const __nv_bfloat16* QH = (const __nv_bfloat16*)(smc + OFF_QH);
    const __nv_bfloat16* QL = (const __nv_bfloat16*)(smc + OFF_QL);
    __nv_bfloat16* PH = (__nv_bfloat16*)(smc + OFF_PH);
    __nv_bfloat16* PL = (__nv_bfloat16*)(smc + OFF_PL);
    float* phiA = (float*)(smc + OFF_PHI);
    float* riA  = (float*)(smc + OFF_RI);

    int t = threadIdx.x;
    int bid = blockIdx.x;
    int rb = bid & 7;
    int unit = bid >> 3;
    int ww = (unit >> 3) & 7, b = unit >> 6;

    int lane = t & 31, wid = t >> 5;
    int g = lane >> 2, tg = lane & 3;
    int m0 = (wid >> 1) * 16;
    int nb = (wid & 1) * 32;

    const __nv_bfloat16* qh = g_qh + (size_t)unit * 32768 + rb * 4096;
    const __nv_bfloat16* ql = g_ql + (size_t)unit * 32768 + rb * 4096;
    const __nv_bfloat16* kh = g_kh + (size_t)unit * 32768;
    const __nv_bfloat16* kl = g_kl + (size_t)unit * 32768;
    const __nv_bfloat16* vh = g_vh + (size_t)unit * 32768;
    const __nv_bfloat16* vl = g_vl + (size_t)unit * 32768;

    // 64 rows x 128B copy into 144B-stride smem (conflict-free per phase)
    int crow = t >> 3, cseg = t & 7;           // 32 rows per 256-thread pass
    #define CPY64(dstoff, srcp, rstride) do {                                   \
        _Pragma("unroll")                                                       \
        for (int k_ = 0; k_ < 2; k_++) {                                        \
            int row_ = crow + k_ * 32;                                          \
            CP16(sb + (dstoff) + row_ * 144 + cseg * 16,                        \
                 (const char*)((srcp) + (size_t)row_ * (rstride)) + cseg * 16); \
        }                                                                       \
    } while (0)

    // prologue: Q + K chunk0 as group 0
    CPY64(OFF_QH, qh, 64);
    CPY64(OFF_QL, ql, 64);
    CPY64(OFF_K0H, kh, 64);
    CPY64(OFF_K0H + 9216, kl, 64);
    CPCOMMIT();

    // phi
    for (int s = t; s < 512; s += 256) {
        int rp = s >> 3, cp = ww * 8 + (s & 7);
        phiA[s] = polar[(((size_t)b * 64 + rp) * 64 + cp) * 2 + 1];
    }

    // ---- Phase 1: S = Qs @ K^T ----
    for (int jc = 0; jc < 8; jc++) {
        if (jc) __syncthreads();                 // prev MMA done -> buffer reusable
        if (jc < 7) {
            uint32_t bo = OFF_K0H + ((jc + 1) & 1) * 18432;
            CPY64(bo, kh + (jc + 1) * 4096, 64);
            CPY64(bo + 9216, kl + (jc + 1) * 4096, 64);
        } else {                                  // prefetch V chunk 0 into buf 0
            CPY64(OFF_K0H, vh, 512);
            CPY64(OFF_K0H + 9216, vl, 512);
        }
        CPCOMMIT();
        CPWAIT1();
        __syncthreads();                          // chunk jc ready CTA-wide

        const __nv_bfloat16* KH = (const __nv_bfloat16*)(smc + OFF_K0H + (jc & 1) * 18432);
        const __nv_bfloat16* KL = KH + 4608;

        float acc[4][4];
        #pragma unroll
        for (int nt = 0; nt < 4; nt++)
            #pragma unroll
            for (int e = 0; e < 4; e++) acc[nt][e] = 0.f;

        #pragma unroll
        for (int term = 0; term < 3; term++) {
            const __nv_bfloat16* A = (term == 2) ? QL : QH;
            const __nv_bfloat16* B = (term == 1) ? KL : KH;
            #pragma unroll
            for (int kt = 0; kt < 4; kt++) {
                int k0 = kt * 16 + tg * 2;
                uint32_t a0 = *(const uint32_t*)&A[(m0 + g)     * BST + k0];
                uint32_t a1 = *(const uint32_t*)&A[(m0 + g + 8) * BST + k0];
                uint32_t a2 = *(const uint32_t*)&A[(m0 + g)     * BST + k0 + 8];
                uint32_t a3 = *(const uint32_t*)&A[(m0 + g + 8) * BST + k0 + 8];
                #pragma unroll
                for (int nt = 0; nt < 4; nt++) {
                    int n = nb + nt * 8 + g;
                    uint32_t b0 = *(const uint32_t*)&B[n * BST + k0];
                    uint32_t b1 = *(const uint32_t*)&B[n * BST + k0 + 8];
                    mma16816(acc[nt], a0, a1, a2, a3, b0, b1);
                }
            }
        }
        #pragma unroll
        for (int nt = 0; nt < 4; nt++) {
            int col = jc * 64 + nb + nt * 8 + tg * 2;
            *(float2*)&S[(m0 + g)     * SST + col] = make_float2(acc[nt][0], acc[nt][1]);
            *(float2*)&S[(m0 + g + 8) * SST + col] = make_float2(acc[nt][2], acc[nt][3]);
        }
    }

    // ---- L1 row sums (with RPE) ----
    __syncthreads();
    {
        int row = t >> 2, quad = t & 3;
        float phq = phiA[rb * 64 + row];
        float ssum = 0.f;
        for (int j4 = quad * 4; j4 < 512; j4 += 16) {
            float4 v = *(float4*)&S[row * SST + j4];
            float4 p = *(const float4*)&phiA[j4];
            ssum += fabsf(v.x + phq - p.x) + fabsf(v.y + phq - p.y)
                  + fabsf(v.z + phq - p.z) + fabsf(v.w + phq - p.w);
        }
        ssum += __shfl_xor_sync(0xffffffffu, ssum, 1);
        ssum += __shfl_xor_sync(0xffffffffu, ssum, 2);
        if (quad == 0) riA[row] = 1.5707963267948966f / (ssum + 1e-8f);
    }
    __syncthreads();

    // ---- Phase 2: activate P chunk, P @ V^T accumulate ----
    const float K1 =  0.5f;
    const float K2 = -1.f / 24.f;
    const float K3 =  1.f / 720.f;
    const float K4 = -1.f / 40320.f;
    const float K5 =  1.f / 3628800.f;
    const float K6 = -1.f / 479001600.f;

    float oacc[4][4];
    #pragma unroll
    for (int nt = 0; nt < 4; nt++)
        #pragma unroll
        for (int e = 0; e < 4; e++) oacc[nt][e] = 0.f;

    int prow = t >> 2, pc0 = (t & 3) * 16;
    float my_ri = riA[prow];
    float my_pq = phiA[rb * 64 + prow];

    for (int jc = 0; jc < 8; jc++) {
        if (jc) __syncthreads();                  // prev MMA done -> V buf + P reusable
        if (jc < 7) {
            uint32_t bo = OFF_K0H + ((jc + 1) & 1) * 18432;
            CPY64(bo, vh + (jc + 1) * 64, 512);
            CPY64(bo + 9216, vl + (jc + 1) * 64, 512);
            CPCOMMIT();
        }
        // activate chunk jc (overlaps the async copy)
        #pragma unroll
        for (int qq = 0; qq < 4; qq++) {
            int j0 = pc0 + qq * 4;
            float4 v = *(float4*)&S[prow * SST + jc * 64 + j0];
            float4 pk = *(const float4*)&phiA[jc * 64 + j0];
            float xs[4] = {v.x + my_pq - pk.x, v.y + my_pq - pk.y,
                           v.z + my_pq - pk.z, v.w + my_pq - pk.w};
            #pragma unroll
            for (int e = 0; e < 4; e++) {
                float x = xs[e] * my_ri;
                float z = x * x;
                float p = fmaf(z, K6, K5);
                p = fmaf(z, p, K4);
                p = fmaf(z, p, K3);
                p = fmaf(z, p, K2);
                p = fmaf(z, p, K1);
                xs[e] = z * p;
            }
            __nv_bfloat16 h0, l0, h1, l1, h2, l2, h3, l3;
            split1(xs[0], h0, l0); split1(xs[1], h1, l1);
            split1(xs[2], h2, l2); split1(xs[3], h3, l3);
            *(uint32_t*)&PH[prow * BST + j0]     = packbf(h0, h1);
            *(uint32_t*)&PH[prow * BST + j0 + 2] = packbf(h2, h3);
            *(uint32_t*)&PL[prow * BST + j0]     = packbf(l0, l1);
            *(uint32_t*)&PL[prow * BST + j0 + 2] = packbf(l2, l3);
        }
        if (jc < 7) { CPWAIT1(); } else { CPWAIT0(); }
        __syncthreads();                          // P + V chunk ready

        const __nv_bfloat16* VH = (const __nv_bfloat16*)(smc + OFF_K0H + (jc & 1) * 18432);
        const __nv_bfloat16* VL = VH + 4608;

        #pragma unroll
        for (int term = 0; term < 3; term++) {
            const __nv_bfloat16* A = (term == 2) ? PL : PH;
            const __nv_bfloat16* B = (term == 1) ? VL : VH;
            #pragma unroll
            for (int kt = 0; kt < 4; kt++) {
                int k0 = kt * 16 + tg * 2;
                uint32_t a0 = *(const uint32_t*)&A[(m0 + g)     * BST + k0];
                uint32_t a1 = *(const uint32_t*)&A[(m0 + g + 8) * BST + k0];
                uint32_t a2 = *(const uint32_t*)&A[(m0 + g)     * BST + k0 + 8];
                uint32_t a3 = *(const uint32_t*)&A[(m0 + g + 8) * BST + k0 + 8];
                #pragma unroll
                for (int nt = 0; nt < 4; nt++) {
                    int n = nb + nt * 8 + g;
                    uint32_t b0 = *(const uint32_t*)&B[n * BST + k0];
                    uint32_t b1 = *(const uint32_t*)&B[n * BST + k0 + 8];
                    mma16816(oacc[nt], a0, a1, a2, a3, b0, b1);
                }
            }
        }
    }

    // ---- Epilogue: RMW into out (lepe base already written) ----
    {
        int h = unit & 7;
        int sg0 = rb * 64 + m0 + g;
        int sg1 = sg0 + 8;
        int sp0 = (sg0 >> 3) * 64 + ww * 8 + (sg0 & 7);
        int sp1 = (sg1 >> 3) * 64 + ww * 8 + (sg1 & 7);
        float* o0 = out + ((size_t)b * 4096 + sp0) * CDIM + h * HD;
        float* o1 = out + ((size_t)b * 4096 + sp1) * CDIM + h * HD;
        #pragma unroll
        for (int nt = 0; nt < 4; nt++) {
            int d0 = nb + nt * 8 + tg * 2;
            float2 c0 = *(float2*)&o0[d0];
            c0.x += oacc[nt][0]; c0.y += oacc[nt][1];
            *(float2*)&o0[d0] = c0;
            float2 c1 = *(float2*)&o1[d0];
            c1.x += oacc[nt][2]; c1.y += oacc[nt][3];
            *(float2*)&o1[d0] = c1;
        }
    }
}

// ---------------------------------------------------------------------------
extern "C" void kernel_launch(void* const* d_in, const int* in_sizes, int n_in,
                              void* d_out, int out_size) {
    const float* temp  = (const float*)d_in[0];  // [3, 8, 512, 64, 64]
    const float* polar = (const float*)d_in[1];  // [8, 64, 64, 2]
    const float* cw    = (const float*)d_in[2];  // [512, 1, 3, 3]
    const float* cb    = (const float*)d_in[3];  // [512]
    float* out = (float*)d_out;                  // [8, 4096, 512]

    const float* v = temp + 2 * PLANE_ALL;

    size_t smA = (size_t)(64 * 195 + 576 + 64) * sizeof(float);
    cudaFuncSetAttribute(lepe_kernel, cudaFuncAttributeMaxDynamicSharedMemorySize, (int)smA);
    cudaFuncSetAttribute(attn_mma_kernel, cudaFuncAttributeMaxDynamicSharedMemorySize, SMEM_ATTN);

    prep_qk<<<UNITS * 16, 256>>>(temp);
    prep_v<<<UNITS * 4, 256>>>(temp);

    dim3 gA(BATCH * 64, CDIM / 64);
    lepe_kernel<<<gA, 256, smA>>>(v, cw, cb, out);
    attn_mma_kernel<<<4096, 256, SMEM_ATTN>>>(polar, out);
}

// round 9
// speedup vs baseline: 2.4433x; 1.0861x over previous
#include <cuda_runtime.h>
#include <cuda_bf16.h>
#include <stdint.h>
#include <math.h>

#define BATCH   8
#define CDIM    512
#define HD      64
#define UNITS   512
#define PLANE_ALL ((size_t)BATCH * CDIM * 64 * 64)

// ---- bf16 hi/lo scratch in operand layouts ----
// Q/K: [unit][token 512][d 64]  (128B rows)   V: [unit][d 64][j 512]
__device__ __nv_bfloat16 g_qh[(size_t)UNITS * 32768];
__device__ __nv_bfloat16 g_ql[(size_t)UNITS * 32768];
__device__ __nv_bfloat16 g_kh[(size_t)UNITS * 32768];
__device__ __nv_bfloat16 g_kl[(size_t)UNITS * 32768];
__device__ __nv_bfloat16 g_vh[(size_t)UNITS * 32768];
__device__ __nv_bfloat16 g_vl[(size_t)UNITS * 32768];

// ---- attn smem byte offsets ----
#define OFF_S    0          /* 64 x 516 f32 = 132096 */
#define OFF_QH   132096
#define OFF_QL   141312
#define OFF_K0H  150528     /* double-buffered K/V chunk: pair stride 18432 */
#define OFF_PH   187392
#define OFF_PL   196608
#define OFF_PHI  205824     /* 512 f32 */
#define OFF_RI   207872     /* 64 f32 */
#define OFF_SUM2 208128     /* 128 f32 */
#define SMEM_ATTN 208640

#define SST 516
#define BST 72      /* bf16 row stride (144B): frag loads conflict-free */

__device__ __forceinline__ void split1(float x, __nv_bfloat16& h, __nv_bfloat16& l) {
    h = __float2bfloat16(x);
    l = __float2bfloat16(x - __bfloat162float(h));
}
__device__ __forceinline__ uint32_t packbf(__nv_bfloat16 a, __nv_bfloat16 c) {
    return (uint32_t)__bfloat16_as_ushort(a) | ((uint32_t)__bfloat16_as_ushort(c) << 16);
}
__device__ __forceinline__ uint32_t smem_u32(const void* p) {
    uint32_t a;
    asm("{ .reg .u64 t; cvta.to.shared.u64 t, %1; cvt.u32.u64 %0, t; }" : "=r"(a) : "l"(p));
    return a;
}
__device__ __forceinline__ void mma16816(float* c, uint32_t a0, uint32_t a1,
                                         uint32_t a2, uint32_t a3,
                                         uint32_t b0, uint32_t b1) {
    asm volatile(
        "mma.sync.aligned.m16n8k16.row.col.f32.bf16.bf16.f32 "
        "{%0,%1,%2,%3}, {%4,%5,%6,%7}, {%8,%9}, {%0,%1,%2,%3};"
        : "+f"(c[0]), "+f"(c[1]), "+f"(c[2]), "+f"(c[3])
        : "r"(a0), "r"(a1), "r"(a2), "r"(a3), "r"(b0), "r"(b1));
}
__device__ __forceinline__ void ldsm_x4(uint32_t& r0, uint32_t& r1, uint32_t& r2,
                                        uint32_t& r3, uint32_t addr) {
    asm volatile("ldmatrix.sync.aligned.m8n8.x4.shared.b16 {%0,%1,%2,%3}, [%4];"
                 : "=r"(r0), "=r"(r1), "=r"(r2), "=r"(r3) : "r"(addr));
}
#define CP16(d, s)  asm volatile("cp.async.cg.shared.global [%0], [%1], 16;" :: "r"(d), "l"(s))
#define CPCOMMIT()  asm volatile("cp.async.commit_group;" ::: "memory")
#define CPWAIT1()   asm volatile("cp.async.wait_group 1;" ::: "memory")
#define CPWAIT0()   asm volatile("cp.async.wait_group 0;" ::: "memory")

// ---------------------------------------------------------------------------
// Pre-pass 1: Q (scaled) and K -> bf16 hi/lo scratch [unit][token][d]
// ---------------------------------------------------------------------------
__global__ __launch_bounds__(256)
void prep_qk(const float* __restrict__ temp) {
    __shared__ __nv_bfloat16 sh[64 * BST];
    __shared__ __nv_bfloat16 sl[64 * BST];
    int bid = blockIdx.x;
    int tsel = bid & 1, jc = (bid >> 1) & 7, unit = bid >> 4;
    int h = unit & 7, ww = (unit >> 3) & 7, b = unit >> 6;
    const float* src = temp + (size_t)tsel * PLANE_ALL + ((size_t)b * CDIM + h * HD) * 4096;
    float scale = tsel ? 1.f : 0.125f;

    int t = threadIdx.x, lane = t & 31, w = t >> 5;
    int j = w * 8 + (lane & 7);
    int jg = jc * 64 + j;
    int sp = (jg >> 3) * 64 + ww * 8 + (jg & 7);
    const float* col = src + sp;

    #pragma unroll
    for (int it = 0; it < 8; it++) {
        int d = (it * 4 + (lane >> 3)) * 2;
        float a = scale * col[(size_t)d * 4096];
        float c = scale * col[(size_t)(d + 1) * 4096];
        __nv_bfloat16 ah, al, ch, cl;
        split1(a, ah, al); split1(c, ch, cl);
        *(uint32_t*)((char*)sh + j * 144 + d * 2) = packbf(ah, ch);
        *(uint32_t*)((char*)sl + j * 144 + d * 2) = packbf(al, cl);
    }
    __syncthreads();

    __nv_bfloat16* dh = (tsel ? g_kh : g_qh) + (size_t)unit * 32768 + jc * 4096;
    __nv_bfloat16* dl = (tsel ? g_kl : g_ql) + (size_t)unit * 32768 + jc * 4096;
    int seg = lane & 7, r4 = lane >> 3;
    #pragma unroll
    for (int it = 0; it < 2; it++) {
        int r = w * 8 + it * 4 + r4;
        *(uint4*)((char*)(dh + r * 64) + seg * 16) = *(uint4*)((char*)sh + r * 144 + seg * 16);
        *(uint4*)((char*)(dl + r * 64) + seg * 16) = *(uint4*)((char*)sl + r * 144 + seg * 16);
    }
}

// ---------------------------------------------------------------------------
// Pre-pass 2: V -> bf16 hi/lo scratch [unit][d][j]
// ---------------------------------------------------------------------------
__global__ __launch_bounds__(256)
void prep_v(const float* __restrict__ temp) {
    int bid = blockIdx.x;
    int unit = bid >> 2, d0 = (bid & 3) * 16;
    int h = unit & 7, ww = (unit >> 3) & 7, b = unit >> 6;
    const float* vb = temp + 2 * PLANE_ALL + ((size_t)b * CDIM + h * HD) * 4096;
    int t = threadIdx.x;
    #pragma unroll
    for (int it = 0; it < 16; it++) {
        int pid = it * 256 + t;
        int j = (pid & 255) * 2;
        int d = d0 + (pid >> 8);
        int sp = (j >> 3) * 64 + ww * 8 + (j & 7);
        float2 x = *(const float2*)&vb[(size_t)d * 4096 + sp];
        __nv_bfloat16 ah, al, ch, cl;
        split1(x.x, ah, al); split1(x.y, ch, cl);
        size_t o = (size_t)unit * 32768 + d * 512 + j;
        *(uint32_t*)&g_vh[o] = packbf(ah, ch);
        *(uint32_t*)&g_vl[o] = packbf(al, cl);
    }
}

// ---------------------------------------------------------------------------
// Kernel A: depthwise 3x3 conv (lepe) -> writes base output layer
// ---------------------------------------------------------------------------
__global__ __launch_bounds__(256)
void lepe_kernel(const float* __restrict__ v, const float* __restrict__ cw,
                 const float* __restrict__ cb, float* __restrict__ out) {
    extern __shared__ float sm[];
    float* vs = sm;
    float* ws = vs + 64 * 195;
    float* bs = ws + 576;

    int bx = blockIdx.x;
    int b = bx >> 6, row = bx & 63;
    int c0 = blockIdx.y * 64;
    int t = threadIdx.x;

    for (int idx = t; idx < 64 * 3 * 64; idx += 256) {
        int c = idx / 192, rem = idx - c * 192;
        int r = rem >> 6, col = rem & 63;
        int gr = row + r - 1;
        float val = 0.f;
        if (gr >= 0 && gr < 64)
            val = v[(((size_t)b * CDIM + c0 + c) * 64 + gr) * 64 + col];
        vs[c * 195 + r * 65 + col] = val;
    }
    for (int idx = t; idx < 576; idx += 256) ws[idx] = cw[(size_t)c0 * 9 + idx];
    if (t < 64) bs[t] = cb[c0 + t];
    __syncthreads();

    int c = t & 63, cg = t >> 6;
    float w0 = ws[c*9+0], w1 = ws[c*9+1], w2 = ws[c*9+2];
    float w3 = ws[c*9+3], w4 = ws[c*9+4], w5 = ws[c*9+5];
    float w6 = ws[c*9+6], w7 = ws[c*9+7], w8 = ws[c*9+8];
    float bias = bs[c];
    const float* base = &vs[c * 195];

    #pragma unroll
    for (int it = 0; it < 16; it++) {
        int col = it * 4 + cg;
        float l0 = (col > 0)  ? base[0*65 + col - 1] : 0.f;
        float l1 = (col > 0)  ? base[1*65 + col - 1] : 0.f;
        float l2 = (col > 0)  ? base[2*65 + col - 1] : 0.f;
        float m0 = base[0*65 + col], m1 = base[1*65 + col], m2 = base[2*65 + col];
        float r0 = (col < 63) ? base[0*65 + col + 1] : 0.f;
        float r1 = (col < 63) ? base[1*65 + col + 1] : 0.f;
        float r2 = (col < 63) ? base[2*65 + col + 1] : 0.f;
        float sum = bias;
        sum += l0*w0 + m0*w1 + r0*w2;
        sum += l1*w3 + m1*w4 + r1*w5;
        sum += l2*w6 + m2*w7 + r2*w8;
        out[((size_t)b * 4096 + row * 64 + col) * CDIM + c0 + c] = sum;
    }
}

// ---------------------------------------------------------------------------
// Kernel B: attention. mma.sync bf16 3-term split, ldmatrix frags,
// Q frags in registers, rpe folded into S, register row-sums.
// CTA = (unit, 64-query block). grid 4096, 256 threads.
// ---------------------------------------------------------------------------
__global__ __launch_bounds__(256, 1)
void attn_mma_kernel(const float* __restrict__ polar, float* __restrict__ out) {
    extern __shared__ char smc[];
    const uint32_t sb = smem_u32(smc);
    float* S = (float*)(smc + OFF_S);
    __nv_bfloat16* PH = (__nv_bfloat16*)(smc + OFF_PH);
    __nv_bfloat16* PL = (__nv_bfloat16*)(smc + OFF_PL);
    float* phiA = (float*)(smc + OFF_PHI);
    float* riA  = (float*)(smc + OFF_RI);
    float* sum2 = (float*)(smc + OFF_SUM2);

    int t = threadIdx.x;
    int bid = blockIdx.x;
    int rb = bid & 7;
    int unit = bid >> 3;
    int ww = (unit >> 3) & 7, b = unit >> 6;

    int lane = t & 31, wid = t >> 5;
    int g = lane >> 2, tg = lane & 3;
    int m0 = (wid >> 1) * 16;
    int nb = (wid & 1) * 32;

    // ldmatrix lane roles
    int lrow = lane & 7, lsel = lane >> 3;
    // A-pattern (m16k16 x4): rows m0 + (lsel&1)*8 + lrow, col (lsel>>1)*8 (+kt*16)
    uint32_t a_off = (uint32_t)((m0 + (lsel & 1) * 8 + lrow) * 144 + (lsel >> 1) * 16);
    // B-pattern (n8k32 x4 per nt): rows nb + nt*8 + lrow, col lsel*8 (+kt2*32)
    uint32_t b_off = (uint32_t)((nb + lrow) * 144 + lsel * 16);

    const __nv_bfloat16* qh = g_qh + (size_t)unit * 32768 + rb * 4096;
    const __nv_bfloat16* ql = g_ql + (size_t)unit * 32768 + rb * 4096;
    const __nv_bfloat16* kh = g_kh + (size_t)unit * 32768;
    const __nv_bfloat16* kl = g_kl + (size_t)unit * 32768;
    const __nv_bfloat16* vh = g_vh + (size_t)unit * 32768;
    const __nv_bfloat16* vl = g_vl + (size_t)unit * 32768;

    // 64 rows x 128B copy into 144B-stride smem (conflict-free per phase)
    int crow = t >> 3, cseg = t & 7;
    #define CPY64(dstoff, srcp, rstride) do {                                   \
        _Pragma("unroll")                                                       \
        for (int k_ = 0; k_ < 2; k_++) {                                        \
            int row_ = crow + k_ * 32;                                          \
            CP16(sb + (dstoff) + row_ * 144 + cseg * 16,                        \
                 (const char*)((srcp) + (size_t)row_ * (rstride)) + cseg * 16); \
        }                                                                       \
    } while (0)

    // prologue: G0 = Q + K0
    CPY64(OFF_QH, qh, 64);
    CPY64(OFF_QL, ql, 64);
    CPY64(OFF_K0H, kh, 64);
    CPY64(OFF_K0H + 9216, kl, 64);
    CPCOMMIT();

    // phi (before first sync)
    for (int s = t; s < 512; s += 256) {
        int rp = s >> 3, cp = ww * 8 + (s & 7);
        phiA[s] = polar[(((size_t)b * 64 + rp) * 64 + cp) * 2 + 1];
    }

    // G1 = K1
    CPY64(OFF_K0H + 18432, kh + 4096, 64);
    CPY64(OFF_K0H + 18432 + 9216, kl + 4096, 64);
    CPCOMMIT();

    CPWAIT1();            // G0 done: Q + K0 ready
    __syncthreads();

    // ---- Q fragments -> registers (invariant over all chunks) ----
    uint32_t aqh[4][4], aql[4][4];
    #pragma unroll
    for (int kt = 0; kt < 4; kt++) {
        ldsm_x4(aqh[kt][0], aqh[kt][1], aqh[kt][2], aqh[kt][3],
                sb + OFF_QH + a_off + kt * 32);
        ldsm_x4(aql[kt][0], aql[kt][1], aql[kt][2], aql[kt][3],
                sb + OFF_QL + a_off + kt * 32);
    }

    float phq0 = phiA[rb * 64 + m0 + g];
    float phq1 = phiA[rb * 64 + m0 + g + 8];
    float rs0 = 0.f, rs1 = 0.f;

    // ---- Phase 1: S = Qs @ K^T + rpe ----
    for (int jc = 0; jc < 8; jc++) {
        uint32_t kbase = OFF_K0H + (uint32_t)(jc & 1) * 18432;

        // cache KH fragments (used by terms 0 and 2)
        uint32_t bkh[2][4][4];
        #pragma unroll
        for (int kt2 = 0; kt2 < 2; kt2++)
            #pragma unroll
            for (int nt = 0; nt < 4; nt++)
                ldsm_x4(bkh[kt2][nt][0], bkh[kt2][nt][1], bkh[kt2][nt][2], bkh[kt2][nt][3],
                        sb + kbase + b_off + nt * 1152 + kt2 * 64);

        float acc[4][4];
        #pragma unroll
        for (int nt = 0; nt < 4; nt++)
            #pragma unroll
            for (int e = 0; e < 4; e++) acc[nt][e] = 0.f;

        // term 0: QH x KH
        #pragma unroll
        for (int kt2 = 0; kt2 < 2; kt2++)
            #pragma unroll
            for (int nt = 0; nt < 4; nt++) {
                mma16816(acc[nt], aqh[2*kt2][0], aqh[2*kt2][1], aqh[2*kt2][2], aqh[2*kt2][3],
                         bkh[kt2][nt][0], bkh[kt2][nt][1]);
                mma16816(acc[nt], aqh[2*kt2+1][0], aqh[2*kt2+1][1], aqh[2*kt2+1][2], aqh[2*kt2+1][3],
                         bkh[kt2][nt][2], bkh[kt2][nt][3]);
            }
        // term 1: QH x KL (streamed)
        #pragma unroll
        for (int kt2 = 0; kt2 < 2; kt2++)
            #pragma unroll
            for (int nt = 0; nt < 4; nt++) {
                uint32_t t0, t1, t2, t3;
                ldsm_x4(t0, t1, t2, t3,
                        sb + kbase + 9216 + b_off + nt * 1152 + kt2 * 64);
                mma16816(acc[nt], aqh[2*kt2][0], aqh[2*kt2][1], aqh[2*kt2][2], aqh[2*kt2][3], t0, t1);
                mma16816(acc[nt], aqh[2*kt2+1][0], aqh[2*kt2+1][1], aqh[2*kt2+1][2], aqh[2*kt2+1][3], t2, t3);
            }
        // term 2: QL x KH
        #pragma unroll
        for (int kt2 = 0; kt2 < 2; kt2++)
            #pragma unroll
            for (int nt = 0; nt < 4; nt++) {
                mma16816(acc[nt], aql[2*kt2][0], aql[2*kt2][1], aql[2*kt2][2], aql[2*kt2][3],
                         bkh[kt2][nt][0], bkh[kt2][nt][1]);
                mma16816(acc[nt], aql[2*kt2+1][0], aql[2*kt2+1][1], aql[2*kt2+1][2], aql[2*kt2+1][3],
                         bkh[kt2][nt][2], bkh[kt2][nt][3]);
            }

        // fold rpe, accumulate row L1 partials, store S
        #pragma unroll
        for (int nt = 0; nt < 4; nt++) {
            int col = jc * 64 + nb + nt * 8 + tg * 2;
            float2 pk = *(const float2*)&phiA[col];
            float s0 = acc[nt][0] + phq0 - pk.x;
            float s1 = acc[nt][1] + phq0 - pk.y;
            float s2 = acc[nt][2] + phq1 - pk.x;
            float s3 = acc[nt][3] + phq1 - pk.y;
            rs0 += fabsf(s0) + fabsf(s1);
            rs1 += fabsf(s2) + fabsf(s3);
            *(float2*)&S[(m0 + g)     * SST + col] = make_float2(s0, s1);
            *(float2*)&S[(m0 + g + 8) * SST + col] = make_float2(s2, s3);
        }

        __syncthreads();                         // chunk jc consumed -> buf reusable
        if (jc < 6) {
            uint32_t bo = OFF_K0H + (uint32_t)(jc & 1) * 18432;
            CPY64(bo, kh + (jc + 2) * 4096, 64);
            CPY64(bo + 9216, kl + (jc + 2) * 4096, 64);
            CPCOMMIT();
        } else if (jc == 6) {                     // prefetch V0 into buf 0
            CPY64(OFF_K0H, vh, 512);
            CPY64(OFF_K0H + 9216, vl, 512);
            CPCOMMIT();
        }
        if (jc < 7) {
            CPWAIT1();                            // chunk jc+1 ready
            __syncthreads();
        }
    }

    // ---- row L1 -> ri (register partials + tiny smem reduce) ----
    rs0 += __shfl_xor_sync(0xffffffffu, rs0, 1);
    rs0 += __shfl_xor_sync(0xffffffffu, rs0, 2);
    rs1 += __shfl_xor_sync(0xffffffffu, rs1, 1);
    rs1 += __shfl_xor_sync(0xffffffffu, rs1, 2);
    __syncthreads();                              // phase-1 done (also S visible)
    if (tg == 0) {
        sum2[(m0 + g) * 2 + (wid & 1)]     = rs0;
        sum2[(m0 + g + 8) * 2 + (wid & 1)] = rs1;
    }
    __syncthreads();
    if (t < 64) riA[t] = 1.5707963267948966f / (sum2[t * 2] + sum2[t * 2 + 1] + 1e-8f);
    __syncthreads();

    // ---- Phase 2: activate P (rpe already in S), P @ V^T accumulate ----
    const float K1 =  0.5f;
    const float K2 = -1.f / 24.f;
    const float K3 =  1.f / 720.f;
    const float K4 = -1.f / 40320.f;
    const float K5 =  1.f / 3628800.f;
    const float K6 = -1.f / 479001600.f;

    float oacc[4][4];
    #pragma unroll
    for (int nt = 0; nt < 4; nt++)
        #pragma unroll
        for (int e = 0; e < 4; e++) oacc[nt][e] = 0.f;

    int prow = t >> 2, pc0 = (t & 3) * 16;
    float my_ri = riA[prow];

    for (int jc = 0; jc < 8; jc++) {
        if (jc < 7) {
            uint32_t bo = OFF_K0H + (uint32_t)((jc + 1) & 1) * 18432;
            CPY64(bo, vh + (jc + 1) * 64, 512);
            CPY64(bo + 9216, vl + (jc + 1) * 64, 512);
            CPCOMMIT();
        }
        // activation (overlaps async copy)
        #pragma unroll
        for (int qq = 0; qq < 4; qq++) {
            int j0 = pc0 + qq * 4;
            float4 v = *(float4*)&S[prow * SST + jc * 64 + j0];
            float xs[4] = {v.x, v.y, v.z, v.w};
            #pragma unroll
            for (int e = 0; e < 4; e++) {
                float x = xs[e] * my_ri;
                float z = x * x;
                float p = fmaf(z, K6, K5);
                p = fmaf(z, p, K4);
                p = fmaf(z, p, K3);
                p = fmaf(z, p, K2);
                p = fmaf(z, p, K1);
                xs[e] = z * p;
            }
            __nv_bfloat16 h0, l0, h1, l1, h2, l2, h3, l3;
            split1(xs[0], h0, l0); split1(xs[1], h1, l1);
            split1(xs[2], h2, l2); split1(xs[3], h3, l3);
            *(uint32_t*)&PH[prow * BST + j0]     = packbf(h0, h1);
            *(uint32_t*)&PH[prow * BST + j0 + 2] = packbf(h2, h3);
            *(uint32_t*)&PL[prow * BST + j0]     = packbf(l0, l1);
            *(uint32_t*)&PL[prow * BST + j0 + 2] = packbf(l2, l3);
        }
        if (jc < 7) { CPWAIT1(); } else { CPWAIT0(); }
        __syncthreads();                          // P + V chunk jc ready

        uint32_t vbase = OFF_K0H + (uint32_t)(jc & 1) * 18432;

        // cache P frags (PH used by 2 terms) and VH frags (used by 2 terms)
        uint32_t aph[4][4], apl[4][4], bvh[2][4][4];
        #pragma unroll
        for (int kt = 0; kt < 4; kt++) {
            ldsm_x4(aph[kt][0], aph[kt][1], aph[kt][2], aph[kt][3],
                    sb + OFF_PH + a_off + kt * 32);
            ldsm_x4(apl[kt][0], apl[kt][1], apl[kt][2], apl[kt][3],
                    sb + OFF_PL + a_off + kt * 32);
        }
        #pragma unroll
        for (int kt2 = 0; kt2 < 2; kt2++)
            #pragma unroll
            for (int nt = 0; nt < 4; nt++)
                ldsm_x4(bvh[kt2][nt][0], bvh[kt2][nt][1], bvh[kt2][nt][2], bvh[kt2][nt][3],
                        sb + vbase + b_off + nt * 1152 + kt2 * 64);

        // term 0: PH x VH
        #pragma unroll
        for (int kt2 = 0; kt2 < 2; kt2++)
            #pragma unroll
            for (int nt = 0; nt < 4; nt++) {
                mma16816(oacc[nt], aph[2*kt2][0], aph[2*kt2][1], aph[2*kt2][2], aph[2*kt2][3],
                         bvh[kt2][nt][0], bvh[kt2][nt][1]);
                mma16816(oacc[nt], aph[2*kt2+1][0], aph[2*kt2+1][1], aph[2*kt2+1][2], aph[2*kt2+1][3],
                         bvh[kt2][nt][2], bvh[kt2][nt][3]);
            }
        // term 1: PH x VL (streamed)
        #pragma unroll
        for (int kt2 = 0; kt2 < 2; kt2++)
            #pragma unroll
            for (int nt = 0; nt < 4; nt++) {
                uint32_t t0, t1, t2, t3;
                ldsm_x4(t0, t1, t2, t3,
                        sb + vbase + 9216 + b_off + nt * 1152 + kt2 * 64);
                mma16816(oacc[nt], aph[2*kt2][0], aph[2*kt2][1], aph[2*kt2][2], aph[2*kt2][3], t0, t1);
                mma16816(oacc[nt], aph[2*kt2+1][0], aph[2*kt2+1][1], aph[2*kt2+1][2], aph[2*kt2+1][3], t2, t3);
            }
        // term 2: PL x VH
        #pragma unroll
        for (int kt2 = 0; kt2 < 2; kt2++)
            #pragma unroll
            for (int nt = 0; nt < 4; nt++) {
                mma16816(oacc[nt], apl[2*kt2][0], apl[2*kt2][1], apl[2*kt2][2], apl[2*kt2][3],
                         bvh[kt2][nt][0], bvh[kt2][nt][1]);
                mma16816(oacc[nt], apl[2*kt2+1][0], apl[2*kt2+1][1], apl[2*kt2+1][2], apl[2*kt2+1][3],
                         bvh[kt2][nt][2], bvh[kt2][nt][3]);
            }

        __syncthreads();                          // before next P/V overwrite
    }

    // ---- Epilogue: RMW into out (lepe base already written) ----
    {
        int h = unit & 7;
        int sg0 = rb * 64 + m0 + g;
        int sg1 = sg0 + 8;
        int sp0 = (sg0 >> 3) * 64 + ww * 8 + (sg0 & 7);
        int sp1 = (sg1 >> 3) * 64 + ww * 8 + (sg1 & 7);
        float* o0 = out + ((size_t)b * 4096 + sp0) * CDIM + h * HD;
        float* o1 = out + ((size_t)b * 4096 + sp1) * CDIM + h * HD;
        #pragma unroll
        for (int nt = 0; nt < 4; nt++) {
            int d0 = nb + nt * 8 + tg * 2;
            float2 c0 = *(float2*)&o0[d0];
            c0.x += oacc[nt][0]; c0.y += oacc[nt][1];
            *(float2*)&o0[d0] = c0;
            float2 c1 = *(float2*)&o1[d0];
            c1.x += oacc[nt][2]; c1.y += oacc[nt][3];
            *(float2*)&o1[d0] = c1;
        }
    }
}

// ---------------------------------------------------------------------------
extern "C" void kernel_launch(void* const* d_in, const int* in_sizes, int n_in,
                              void* d_out, int out_size) {
    const float* temp  = (const float*)d_in[0];  // [3, 8, 512, 64, 64]
    const float* polar = (const float*)d_in[1];  // [8, 64, 64, 2]
    const float* cw    = (const float*)d_in[2];  // [512, 1, 3, 3]
    const float* cb    = (const float*)d_in[3];  // [512]
    float* out = (float*)d_out;                  // [8, 4096, 512]

    const float* v = temp + 2 * PLANE_ALL;

    size_t smA = (size_t)(64 * 195 + 576 + 64) * sizeof(float);
    cudaFuncSetAttribute(lepe_kernel, cudaFuncAttributeMaxDynamicSharedMemorySize, (int)smA);
    cudaFuncSetAttribute(attn_mma_kernel, cudaFuncAttributeMaxDynamicSharedMemorySize, SMEM_ATTN);

    prep_qk<<<UNITS * 16, 256>>>(temp);
    prep_v<<<UNITS * 4, 256>>>(temp);

    dim3 gA(BATCH * 64, CDIM / 64);
    lepe_kernel<<<gA, 256, smA>>>(v, cw, cb, out);
    attn_mma_kernel<<<4096, 256, SMEM_ATTN>>>(polar, out);
}

// round 11
// speedup vs baseline: 2.8960x; 1.1853x over previous
#include <cuda_runtime.h>
#include <cuda_bf16.h>
#include <stdint.h>
#include <math.h>

#define BATCH   8
#define CDIM    512
#define HD      64
#define UNITS   512
#define PLANE_ALL ((size_t)BATCH * CDIM * 64 * 64)

// ---- bf16 hi/lo scratch in operand layouts ----
// Q/K: [unit][token 512][d 64]  (128B rows)   V: [unit][d 64][j 512]
__device__ __nv_bfloat16 g_qh[(size_t)UNITS * 32768];
__device__ __nv_bfloat16 g_ql[(size_t)UNITS * 32768];
__device__ __nv_bfloat16 g_kh[(size_t)UNITS * 32768];
__device__ __nv_bfloat16 g_kl[(size_t)UNITS * 32768];
__device__ __nv_bfloat16 g_vh[(size_t)UNITS * 32768];
__device__ __nv_bfloat16 g_vl[(size_t)UNITS * 32768];
// S score scratch: [cta 4096][64 rows][512 cols] f32 (L2-resident working set)
__device__ float g_S[(size_t)4096 * 32768];

// ---- attn smem byte offsets (total 76.5 KB -> 2 CTAs/SM) ----
#define OFF_QH   0
#define OFF_QL   9216
#define OFF_K0H  18432     /* double-buffered K/V chunk: pair stride 18432 */
#define OFF_PH   55296
#define OFF_PL   64512
#define OFF_PHI  73728     /* 512 f32 */
#define OFF_RI   75776     /* 64 f32 */
#define OFF_SUM2 76032     /* 128 f32 */
#define SMEM_ATTN 76544

#define BST 72      /* bf16 row stride (144B): frag loads conflict-free */

__device__ __forceinline__ void split1(float x, __nv_bfloat16& h, __nv_bfloat16& l) {
    h = __float2bfloat16(x);
    l = __float2bfloat16(x - __bfloat162float(h));
}
__device__ __forceinline__ uint32_t packbf(__nv_bfloat16 a, __nv_bfloat16 c) {
    return (uint32_t)__bfloat16_as_ushort(a) | ((uint32_t)__bfloat16_as_ushort(c) << 16);
}
__device__ __forceinline__ uint32_t smem_u32(const void* p) {
    uint32_t a;
    asm("{ .reg .u64 t; cvta.to.shared.u64 t, %1; cvt.u32.u64 %0, t; }" : "=r"(a) : "l"(p));
    return a;
}
__device__ __forceinline__ void mma16816(float* c, uint32_t a0, uint32_t a1,
                                         uint32_t a2, uint32_t a3,
                                         uint32_t b0, uint32_t b1) {
    asm volatile(
        "mma.sync.aligned.m16n8k16.row.col.f32.bf16.bf16.f32 "
        "{%0,%1,%2,%3}, {%4,%5,%6,%7}, {%8,%9}, {%0,%1,%2,%3};"
        : "+f"(c[0]), "+f"(c[1]), "+f"(c[2]), "+f"(c[3])
        : "r"(a0), "r"(a1), "r"(a2), "r"(a3), "r"(b0), "r"(b1));
}
__device__ __forceinline__ void ldsm_x4(uint32_t& r0, uint32_t& r1, uint32_t& r2,
                                        uint32_t& r3, uint32_t addr) {
    asm volatile("ldmatrix.sync.aligned.m8n8.x4.shared.b16 {%0,%1,%2,%3}, [%4];"
                 : "=r"(r0), "=r"(r1), "=r"(r2), "=r"(r3) : "r"(addr));
}
#define CP16(d, s)  asm volatile("cp.async.cg.shared.global [%0], [%1], 16;" :: "r"(d), "l"(s))
#define CPCOMMIT()  asm volatile("cp.async.commit_group;" ::: "memory")
#define CPWAIT1()   asm volatile("cp.async.wait_group 1;" ::: "memory")
#define CPWAIT0()   asm volatile("cp.async.wait_group 0;" ::: "memory")

// ---------------------------------------------------------------------------
// Pre-pass 1: Q (scaled) and K -> bf16 hi/lo scratch [unit][token][d]
// ---------------------------------------------------------------------------
__global__ __launch_bounds__(256)
void prep_qk(const float* __restrict__ temp) {
    __shared__ __nv_bfloat16 sh[64 * BST];
    __shared__ __nv_bfloat16 sl[64 * BST];
    int bid = blockIdx.x;
    int tsel = bid & 1, jc = (bid >> 1) & 7, unit = bid >> 4;
    int h = unit & 7, ww = (unit >> 3) & 7, b = unit >> 6;
    const float* src = temp + (size_t)tsel * PLANE_ALL + ((size_t)b * CDIM + h * HD) * 4096;
    float scale = tsel ? 1.f : 0.125f;

    int t = threadIdx.x, lane = t & 31, w = t >> 5;
    int j = w * 8 + (lane & 7);
    int jg = jc * 64 + j;
    int sp = (jg >> 3) * 64 + ww * 8 + (jg & 7);
    const float* col = src + sp;

    #pragma unroll
    for (int it = 0; it < 8; it++) {
        int d = (it * 4 + (lane >> 3)) * 2;
        float a = scale * col[(size_t)d * 4096];
        float c = scale * col[(size_t)(d + 1) * 4096];
        __nv_bfloat16 ah, al, ch, cl;
        split1(a, ah, al); split1(c, ch, cl);
        *(uint32_t*)((char*)sh + j * 144 + d * 2) = packbf(ah, ch);
        *(uint32_t*)((char*)sl + j * 144 + d * 2) = packbf(al, cl);
    }
    __syncthreads();

    __nv_bfloat16* dh = (tsel ? g_kh : g_qh) + (size_t)unit * 32768 + jc * 4096;
    __nv_bfloat16* dl = (tsel ? g_kl : g_ql) + (size_t)unit * 32768 + jc * 4096;
    int seg = lane & 7, r4 = lane >> 3;
    #pragma unroll
    for (int it = 0; it < 2; it++) {
        int r = w * 8 + it * 4 + r4;
        *(uint4*)((char*)(dh + r * 64) + seg * 16) = *(uint4*)((char*)sh + r * 144 + seg * 16);
        *(uint4*)((char*)(dl + r * 64) + seg * 16) = *(uint4*)((char*)sl + r * 144 + seg * 16);
    }
}

// ---------------------------------------------------------------------------
// Pre-pass 2: V -> bf16 hi/lo scratch [unit][d][j]
// ---------------------------------------------------------------------------
__global__ __launch_bounds__(256)
void prep_v(const float* __restrict__ temp) {
    int bid = blockIdx.x;
    int unit = bid >> 2, d0 = (bid & 3) * 16;
    int h = unit & 7, ww = (unit >> 3) & 7, b = unit >> 6;
    const float* vb = temp + 2 * PLANE_ALL + ((size_t)b * CDIM + h * HD) * 4096;
    int t = threadIdx.x;
    #pragma unroll
    for (int it = 0; it < 16; it++) {
        int pid = it * 256 + t;
        int j = (pid & 255) * 2;
        int d = d0 + (pid >> 8);
        int sp = (j >> 3) * 64 + ww * 8 + (j & 7);
        float2 x = *(const float2*)&vb[(size_t)d * 4096 + sp];
        __nv_bfloat16 ah, al, ch, cl;
        split1(x.x, ah, al); split1(x.y, ch, cl);
        size_t o = (size_t)unit * 32768 + d * 512 + j;
        *(uint32_t*)&g_vh[o] = packbf(ah, ch);
        *(uint32_t*)&g_vl[o] = packbf(al, cl);
    }
}

// ---------------------------------------------------------------------------
// Kernel A: depthwise 3x3 conv (lepe) -> writes base output layer
// ---------------------------------------------------------------------------
__global__ __launch_bounds__(256)
void lepe_kernel(const float* __restrict__ v, const float* __restrict__ cw,
                 const float* __restrict__ cb, float* __restrict__ out) {
    extern __shared__ float sm[];
    float* vs = sm;
    float* ws = vs + 64 * 195;
    float* bs = ws + 576;

    int bx = blockIdx.x;
    int b = bx >> 6, row = bx & 63;
    int c0 = blockIdx.y * 64;
    int t = threadIdx.x;

    for (int idx = t; idx < 64 * 3 * 64; idx += 256) {
        int c = idx / 192, rem = idx - c * 192;
        int r = rem >> 6, col = rem & 63;
        int gr = row + r - 1;
        float val = 0.f;
        if (gr >= 0 && gr < 64)
            val = v[(((size_t)b * CDIM + c0 + c) * 64 + gr) * 64 + col];
        vs[c * 195 + r * 65 + col] = val;
    }
    for (int idx = t; idx < 576; idx += 256) ws[idx] = cw[(size_t)c0 * 9 + idx];
    if (t < 64) bs[t] = cb[c0 + t];
    __syncthreads();

    int c = t & 63, cg = t >> 6;
    float w0 = ws[c*9+0], w1 = ws[c*9+1], w2 = ws[c*9+2];
    float w3 = ws[c*9+3], w4 = ws[c*9+4], w5 = ws[c*9+5];
    float w6 = ws[c*9+6], w7 = ws[c*9+7], w8 = ws[c*9+8];
    float bias = bs[c];
    const float* base = &vs[c * 195];

    #pragma unroll
    for (int it = 0; it < 16; it++) {
        int col = it * 4 + cg;
        float l0 = (col > 0)  ? base[0*65 + col - 1] : 0.f;
        float l1 = (col > 0)  ? base[1*65 + col - 1] : 0.f;
        float l2 = (col > 0)  ? base[2*65 + col - 1] : 0.f;
        float m0 = base[0*65 + col], m1 = base[1*65 + col], m2 = base[2*65 + col];
        float r0 = (col < 63) ? base[0*65 + col + 1] : 0.f;
        float r1 = (col < 63) ? base[1*65 + col + 1] : 0.f;
        float r2 = (col < 63) ? base[2*65 + col + 1] : 0.f;
        float sum = bias;
        sum += l0*w0 + m0*w1 + r0*w2;
        sum += l1*w3 + m1*w4 + r1*w5;
        sum += l2*w6 + m2*w7 + r2*w8;
        out[((size_t)b * 4096 + row * 64 + col) * CDIM + c0 + c] = sum;
    }
}

// ---------------------------------------------------------------------------
// Kernel B: attention. mma.sync bf16 3-term split, ldmatrix frags,
// Q frags in registers, rpe folded, register row-sums, S in global (L2).
// CTA = (unit, 64-query block). grid 4096, 256 threads, 2 CTAs/SM.
// ---------------------------------------------------------------------------
__global__ __launch_bounds__(256, 2)
void attn_mma_kernel(const float* __restrict__ polar, float* __restrict__ out) {
    extern __shared__ char smc[];
    const uint32_t sb = smem_u32(smc);
    __nv_bfloat16* PH = (__nv_bfloat16*)(smc + OFF_PH);
    __nv_bfloat16* PL = (__nv_bfloat16*)(smc + OFF_PL);
    float* phiA = (float*)(smc + OFF_PHI);
    float* riA  = (float*)(smc + OFF_RI);
    float* sum2 = (float*)(smc + OFF_SUM2);

    int t = threadIdx.x;
    int bid = blockIdx.x;
    int rb = bid & 7;
    int unit = bid >> 3;
    int ww = (unit >> 3) & 7, b = unit >> 6;

    int lane = t & 31, wid = t >> 5;
    int g = lane >> 2, tg = lane & 3;
    int m0 = (wid >> 1) * 16;
    int nb = (wid & 1) * 32;

    float* Sg = g_S + (size_t)bid * 32768;   // this CTA's 64x512 score tile

    // ldmatrix lane roles
    int lrow = lane & 7, lsel = lane >> 3;
    uint32_t a_off = (uint32_t)((m0 + (lsel & 1) * 8 + lrow) * 144 + (lsel >> 1) * 16);
    uint32_t b_off = (uint32_t)((nb + lrow) * 144 + lsel * 16);

    const __nv_bfloat16* qh = g_qh + (size_t)unit * 32768 + rb * 4096;
    const __nv_bfloat16* ql = g_ql + (size_t)unit * 32768 + rb * 4096;
    const __nv_bfloat16* kh = g_kh + (size_t)unit * 32768;
    const __nv_bfloat16* kl = g_kl + (size_t)unit * 32768;
    const __nv_bfloat16* vh = g_vh + (size_t)unit * 32768;
    const __nv_bfloat16* vl = g_vl + (size_t)unit * 32768;

    int crow = t >> 3, cseg = t & 7;
    #define CPY64(dstoff, srcp, rstride) do {                                   \
        _Pragma("unroll")                                                       \
        for (int k_ = 0; k_ < 2; k_++) {                                        \
            int row_ = crow + k_ * 32;                                          \
            CP16(sb + (dstoff) + row_ * 144 + cseg * 16,                        \
                 (const char*)((srcp) + (size_t)row_ * (rstride)) + cseg * 16); \
        }                                                                       \
    } while (0)

    // prologue: G0 = Q + K0
    CPY64(OFF_QH, qh, 64);
    CPY64(OFF_QL, ql, 64);
    CPY64(OFF_K0H, kh, 64);
    CPY64(OFF_K0H + 9216, kl, 64);
    CPCOMMIT();

    // phi
    for (int s = t; s < 512; s += 256) {
        int rp = s >> 3, cp = ww * 8 + (s & 7);
        phiA[s] = polar[(((size_t)b * 64 + rp) * 64 + cp) * 2 + 1];
    }

    // G1 = K1
    CPY64(OFF_K0H + 18432, kh + 4096, 64);
    CPY64(OFF_K0H + 18432 + 9216, kl + 4096, 64);
    CPCOMMIT();

    CPWAIT1();            // G0 done: Q + K0 ready
    __syncthreads();

    // ---- Q fragments -> registers ----
    uint32_t aqh[4][4], aql[4][4];
    #pragma unroll
    for (int kt = 0; kt < 4; kt++) {
        ldsm_x4(aqh[kt][0], aqh[kt][1], aqh[kt][2], aqh[kt][3],
                sb + OFF_QH + a_off + kt * 32);
        ldsm_x4(aql[kt][0], aql[kt][1], aql[kt][2], aql[kt][3],
                sb + OFF_QL + a_off + kt * 32);
    }

    float phq0 = phiA[rb * 64 + m0 + g];
    float phq1 = phiA[rb * 64 + m0 + g + 8];
    float rs0 = 0.f, rs1 = 0.f;

    // ---- Phase 1: S = Qs @ K^T + rpe -> global S tile ----
    for (int jc = 0; jc < 8; jc++) {
        uint32_t kbase = OFF_K0H + (uint32_t)(jc & 1) * 18432;

        uint32_t bkh[2][4][4];
        #pragma unroll
        for (int kt2 = 0; kt2 < 2; kt2++)
            #pragma unroll
            for (int nt = 0; nt < 4; nt++)
                ldsm_x4(bkh[kt2][nt][0], bkh[kt2][nt][1], bkh[kt2][nt][2], bkh[kt2][nt][3],
                        sb + kbase + b_off + nt * 1152 + kt2 * 64);

        float acc[4][4];
        #pragma unroll
        for (int nt = 0; nt < 4; nt++)
            #pragma unroll
            for (int e = 0; e < 4; e++) acc[nt][e] = 0.f;

        // term 0: QH x KH
        #pragma unroll
        for (int kt2 = 0; kt2 < 2; kt2++)
            #pragma unroll
            for (int nt = 0; nt < 4; nt++) {
                mma16816(acc[nt], aqh[2*kt2][0], aqh[2*kt2][1], aqh[2*kt2][2], aqh[2*kt2][3],
                         bkh[kt2][nt][0], bkh[kt2][nt][1]);
                mma16816(acc[nt], aqh[2*kt2+1][0], aqh[2*kt2+1][1], aqh[2*kt2+1][2], aqh[2*kt2+1][3],
                         bkh[kt2][nt][2], bkh[kt2][nt][3]);
            }
        // term 1: QH x KL (streamed)
        #pragma unroll
        for (int kt2 = 0; kt2 < 2; kt2++)
            #pragma unroll
            for (int nt = 0; nt < 4; nt++) {
                uint32_t t0, t1, t2, t3;
                ldsm_x4(t0, t1, t2, t3,
                        sb + kbase + 9216 + b_off + nt * 1152 + kt2 * 64);
                mma16816(acc[nt], aqh[2*kt2][0], aqh[2*kt2][1], aqh[2*kt2][2], aqh[2*kt2][3], t0, t1);
                mma16816(acc[nt], aqh[2*kt2+1][0], aqh[2*kt2+1][1], aqh[2*kt2+1][2], aqh[2*kt2+1][3], t2, t3);
            }
        // term 2: QL x KH
        #pragma unroll
        for (int kt2 = 0; kt2 < 2; kt2++)
            #pragma unroll
            for (int nt = 0; nt < 4; nt++) {
                mma16816(acc[nt], aql[2*kt2][0], aql[2*kt2][1], aql[2*kt2][2], aql[2*kt2][3],
                         bkh[kt2][nt][0], bkh[kt2][nt][1]);
                mma16816(acc[nt], aql[2*kt2+1][0], aql[2*kt2+1][1], aql[2*kt2+1][2], aql[2*kt2+1][3],
                         bkh[kt2][nt][2], bkh[kt2][nt][3]);
            }

        // fold rpe, accumulate row L1 partials, store S to global (no sync needed)
        #pragma unroll
        for (int nt = 0; nt < 4; nt++) {
            int col = jc * 64 + nb + nt * 8 + tg * 2;
            float2 pk = *(const float2*)&phiA[col];
            float s0 = acc[nt][0] + phq0 - pk.x;
            float s1 = acc[nt][1] + phq0 - pk.y;
            float s2 = acc[nt][2] + phq1 - pk.x;
            float s3 = acc[nt][3] + phq1 - pk.y;
            rs0 += fabsf(s0) + fabsf(s1);
            rs1 += fabsf(s2) + fabsf(s3);
            *(float2*)&Sg[(m0 + g) * 512 + col]     = make_float2(s0, s1);
            *(float2*)&Sg[(m0 + g + 8) * 512 + col] = make_float2(s2, s3);
        }

        __syncthreads();                         // K chunk jc consumed -> buf reusable
        if (jc < 6) {
            uint32_t bo = OFF_K0H + (uint32_t)(jc & 1) * 18432;
            CPY64(bo, kh + (jc + 2) * 4096, 64);
            CPY64(bo + 9216, kl + (jc + 2) * 4096, 64);
            CPCOMMIT();
        } else if (jc == 6) {                     // prefetch V0 into buf 0
            CPY64(OFF_K0H, vh, 512);
            CPY64(OFF_K0H + 9216, vl, 512);
            CPCOMMIT();
        }
        if (jc < 7) {
            CPWAIT1();
            __syncthreads();
        }
    }

    // ---- row L1 -> ri ----
    rs0 += __shfl_xor_sync(0xffffffffu, rs0, 1);
    rs0 += __shfl_xor_sync(0xffffffffu, rs0, 2);
    rs1 += __shfl_xor_sync(0xffffffffu, rs1, 1);
    rs1 += __shfl_xor_sync(0xffffffffu, rs1, 2);
    if (tg == 0) {
        sum2[(m0 + g) * 2 + (wid & 1)]     = rs0;
        sum2[(m0 + g + 8) * 2 + (wid & 1)] = rs1;
    }
    __syncthreads();
    if (t < 64) riA[t] = 1.5707963267948966f / (sum2[t * 2] + sum2[t * 2 + 1] + 1e-8f);
    __syncthreads();

    // ---- Phase 2: activate P (from global S), P @ V^T accumulate ----
    const float K1 =  0.5f;
    const float K2 = -1.f / 24.f;
    const float K3 =  1.f / 720.f;
    const float K4 = -1.f / 40320.f;
    const float K5 =  1.f / 3628800.f;
    const float K6 = -1.f / 479001600.f;

    float oacc[4][4];
    #pragma unroll
    for (int nt = 0; nt < 4; nt++)
        #pragma unroll
        for (int e = 0; e < 4; e++) oacc[nt][e] = 0.f;

    int prow = t >> 2, pc0 = (t & 3) * 16;
    float my_ri = riA[prow];

    for (int jc = 0; jc < 8; jc++) {
        if (jc < 7) {
            uint32_t bo = OFF_K0H + (uint32_t)((jc + 1) & 1) * 18432;
            CPY64(bo, vh + (jc + 1) * 64, 512);
            CPY64(bo + 9216, vl + (jc + 1) * 64, 512);
            CPCOMMIT();
        }
        // activation (reads S from global/L2; overlaps async copy)
        float4 sv[4];
        #pragma unroll
        for (int qq = 0; qq < 4; qq++)
            sv[qq] = *(const float4*)&Sg[prow * 512 + jc * 64 + pc0 + qq * 4];
        #pragma unroll
        for (int qq = 0; qq < 4; qq++) {
            int j0 = pc0 + qq * 4;
            float xs[4] = {sv[qq].x, sv[qq].y, sv[qq].z, sv[qq].w};
            #pragma unroll
            for (int e = 0; e < 4; e++) {
                float x = xs[e] * my_ri;
                float z = x * x;
                float p = fmaf(z, K6, K5);
                p = fmaf(z, p, K4);
                p = fmaf(z, p, K3);
                p = fmaf(z, p, K2);
                p = fmaf(z, p, K1);
                xs[e] = z * p;
            }
            __nv_bfloat16 h0, l0, h1, l1, h2, l2, h3, l3;
            split1(xs[0], h0, l0); split1(xs[1], h1, l1);
            split1(xs[2], h2, l2); split1(xs[3], h3, l3);
            *(uint32_t*)&PH[prow * BST + j0]     = packbf(h0, h1);
            *(uint32_t*)&PH[prow * BST + j0 + 2] = packbf(h2, h3);
            *(uint32_t*)&PL[prow * BST + j0]     = packbf(l0, l1);
            *(uint32_t*)&PL[prow * BST + j0 + 2] = packbf(l2, l3);
        }
        if (jc < 7) { CPWAIT1(); } else { CPWAIT0(); }
        __syncthreads();                          // P + V chunk jc ready

        uint32_t vbase = OFF_K0H + (uint32_t)(jc & 1) * 18432;

        uint32_t aph[4][4], apl[4][4], bvh[2][4][4];
        #pragma unroll
        for (int kt = 0; kt < 4; kt++) {
            ldsm_x4(aph[kt][0], aph[kt][1], aph[kt][2], aph[kt][3],
                    sb + OFF_PH + a_off + kt * 32);
            ldsm_x4(apl[kt][0], apl[kt][1], apl[kt][2], apl[kt][3],
                    sb + OFF_PL + a_off + kt * 32);
        }
        #pragma unroll
        for (int kt2 = 0; kt2 < 2; kt2++)
            #pragma unroll
            for (int nt = 0; nt < 4; nt++)
                ldsm_x4(bvh[kt2][nt][0], bvh[kt2][nt][1], bvh[kt2][nt][2], bvh[kt2][nt][3],
                        sb + vbase + b_off + nt * 1152 + kt2 * 64);

        // term 0: PH x VH
        #pragma unroll
        for (int kt2 = 0; kt2 < 2; kt2++)
            #pragma unroll
            for (int nt = 0; nt < 4; nt++) {
                mma16816(oacc[nt], aph[2*kt2][0], aph[2*kt2][1], aph[2*kt2][2], aph[2*kt2][3],
                         bvh[kt2][nt][0], bvh[kt2][nt][1]);
                mma16816(oacc[nt], aph[2*kt2+1][0], aph[2*kt2+1][1], aph[2*kt2+1][2], aph[2*kt2+1][3],
                         bvh[kt2][nt][2], bvh[kt2][nt][3]);
            }
        // term 1: PH x VL (streamed)
        #pragma unroll
        for (int kt2 = 0; kt2 < 2; kt2++)
            #pragma unroll
            for (int nt = 0; nt < 4; nt++) {
                uint32_t t0, t1, t2, t3;
                ldsm_x4(t0, t1, t2, t3,
                        sb + vbase + 9216 + b_off + nt * 1152 + kt2 * 64);
                mma16816(oacc[nt], aph[2*kt2][0], aph[2*kt2][1], aph[2*kt2][2], aph[2*kt2][3], t0, t1);
                mma16816(oacc[nt], aph[2*kt2+1][0], aph[2*kt2+1][1], aph[2*kt2+1][2], aph[2*kt2+1][3], t2, t3);
            }
        // term 2: PL x VH
        #pragma unroll
        for (int kt2 = 0; kt2 < 2; kt2++)
            #pragma unroll
            for (int nt = 0; nt < 4; nt++) {
                mma16816(oacc[nt], apl[2*kt2][0], apl[2*kt2][1], apl[2*kt2][2], apl[2*kt2][3],
                         bvh[kt2][nt][0], bvh[kt2][nt][1]);
                mma16816(oacc[nt], apl[2*kt2+1][0], apl[2*kt2+1][1], apl[2*kt2+1][2], apl[2*kt2+1][3],
                         bvh[kt2][nt][2], bvh[kt2][nt][3]);
            }

        __syncthreads();                          // before next P/V overwrite
    }

    // ---- Epilogue: RMW into out (lepe base already written) ----
    {
        int h = unit & 7;
        int sg0 = rb * 64 + m0 + g;
        int sg1 = sg0 + 8;
        int sp0 = (sg0 >> 3) * 64 + ww * 8 + (sg0 & 7);
        int sp1 = (sg1 >> 3) * 64 + ww * 8 + (sg1 & 7);
        float* o0 = out + ((size_t)b * 4096 + sp0) * CDIM + h * HD;
        float* o1 = out + ((size_t)b * 4096 + sp1) * CDIM + h * HD;
        #pragma unroll
        for (int nt = 0; nt < 4; nt++) {
            int d0 = nb + nt * 8 + tg * 2;
            float2 c0 = *(float2*)&o0[d0];
            c0.x += oacc[nt][0]; c0.y += oacc[nt][1];
            *(float2*)&o0[d0] = c0;
            float2 c1 = *(float2*)&o1[d0];
            c1.x += oacc[nt][2]; c1.y += oacc[nt][3];
            *(float2*)&o1[d0] = c1;
        }
    }
}

// ---------------------------------------------------------------------------
extern "C" void kernel_launch(void* const* d_in, const int* in_sizes, int n_in,
                              void* d_out, int out_size) {
    const float* temp  = (const float*)d_in[0];  // [3, 8, 512, 64, 64]
    const float* polar = (const float*)d_in[1];  // [8, 64, 64, 2]
    const float* cw    = (const float*)d_in[2];  // [512, 1, 3, 3]
    const float* cb    = (const float*)d_in[3];  // [512]
    float* out = (float*)d_out;                  // [8, 4096, 512]

    const float* v = temp + 2 * PLANE_ALL;

    size_t smA = (size_t)(64 * 195 + 576 + 64) * sizeof(float);
    cudaFuncSetAttribute(lepe_kernel, cudaFuncAttributeMaxDynamicSharedMemorySize, (int)smA);
    cudaFuncSetAttribute(attn_mma_kernel, cudaFuncAttributeMaxDynamicSharedMemorySize, SMEM_ATTN);

    prep_qk<<<UNITS * 16, 256>>>(temp);
    prep_v<<<UNITS * 4, 256>>>(temp);

    dim3 gA(BATCH * 64, CDIM / 64);
    lepe_kernel<<<gA, 256, smA>>>(v, cw, cb, out);
    attn_mma_kernel<<<4096, 256, SMEM_ATTN>>>(polar, out);
}

// round 12
// speedup vs baseline: 2.9924x; 1.0333x over previous
#include <cuda_runtime.h>
#include <cuda_bf16.h>
#include <stdint.h>
#include <math.h>

#define BATCH   8
#define CDIM    512
#define HD      64
#define UNITS   512
#define PLANE_ALL ((size_t)BATCH * CDIM * 64 * 64)

// ---- bf16 hi/lo scratch in operand layouts ----
// Q/K: [unit][token 512][d 64]  (128B rows)   V: [unit][d 64][j 512]
__device__ __nv_bfloat16 g_qh[(size_t)UNITS * 32768];
__device__ __nv_bfloat16 g_ql[(size_t)UNITS * 32768];
__device__ __nv_bfloat16 g_kh[(size_t)UNITS * 32768];
__device__ __nv_bfloat16 g_kl[(size_t)UNITS * 32768];
__device__ __nv_bfloat16 g_vh[(size_t)UNITS * 32768];
__device__ __nv_bfloat16 g_vl[(size_t)UNITS * 32768];
// S scratch, FRAGMENT-LINEAR: [cta][MT 4][CT 64][lane 32] x float4
__device__ float g_S[(size_t)4096 * 32768];

// ---- attn smem byte offsets ----
#define OFF_QH   0
#define OFF_QL   9216
#define OFF_K0H  18432     /* double-buffered K/V chunk: pair stride 18432 */
#define OFF_PHI  55296     /* 512 f32 */
#define OFF_RI   57344     /* 64 f32 */
#define OFF_SUM2 57600     /* 256 f32 */
#define SMEM_ATTN 58624

#define BST 72      /* bf16 row stride (144B): frag loads conflict-free */

__device__ __forceinline__ void split1(float x, __nv_bfloat16& h, __nv_bfloat16& l) {
    h = __float2bfloat16(x);
    l = __float2bfloat16(x - __bfloat162float(h));
}
__device__ __forceinline__ uint32_t packbf(__nv_bfloat16 a, __nv_bfloat16 c) {
    return (uint32_t)__bfloat16_as_ushort(a) | ((uint32_t)__bfloat16_as_ushort(c) << 16);
}
__device__ __forceinline__ uint32_t smem_u32(const void* p) {
    uint32_t a;
    asm("{ .reg .u64 t; cvta.to.shared.u64 t, %1; cvt.u32.u64 %0, t; }" : "=r"(a) : "l"(p));
    return a;
}
__device__ __forceinline__ void mma16816(float* c, uint32_t a0, uint32_t a1,
                                         uint32_t a2, uint32_t a3,
                                         uint32_t b0, uint32_t b1) {
    asm volatile(
        "mma.sync.aligned.m16n8k16.row.col.f32.bf16.bf16.f32 "
        "{%0,%1,%2,%3}, {%4,%5,%6,%7}, {%8,%9}, {%0,%1,%2,%3};"
        : "+f"(c[0]), "+f"(c[1]), "+f"(c[2]), "+f"(c[3])
        : "r"(a0), "r"(a1), "r"(a2), "r"(a3), "r"(b0), "r"(b1));
}
__device__ __forceinline__ void ldsm_x4(uint32_t& r0, uint32_t& r1, uint32_t& r2,
                                        uint32_t& r3, uint32_t addr) {
    asm volatile("ldmatrix.sync.aligned.m8n8.x4.shared.b16 {%0,%1,%2,%3}, [%4];"
                 : "=r"(r0), "=r"(r1), "=r"(r2), "=r"(r3) : "r"(addr));
}
#define CP16(d, s)  asm volatile("cp.async.cg.shared.global [%0], [%1], 16;" :: "r"(d), "l"(s))
#define CPCOMMIT()  asm volatile("cp.async.commit_group;" ::: "memory")
#define CPWAIT1()   asm volatile("cp.async.wait_group 1;" ::: "memory")
#define CPWAIT0()   asm volatile("cp.async.wait_group 0;" ::: "memory")

__device__ __forceinline__ float act1(float s, float ri) {
    const float K1 =  0.5f;
    const float K2 = -1.f / 24.f;
    const float K3 =  1.f / 720.f;
    const float K4 = -1.f / 40320.f;
    const float K5 =  1.f / 3628800.f;
    const float K6 = -1.f / 479001600.f;
    float x = s * ri;
    float z = x * x;
    float p = fmaf(z, K6, K5);
    p = fmaf(z, p, K4);
    p = fmaf(z, p, K3);
    p = fmaf(z, p, K2);
    p = fmaf(z, p, K1);
    return z * p;
}

// ---------------------------------------------------------------------------
// Pre-pass 1: Q (scaled) and K -> bf16 hi/lo scratch [unit][token][d]
// ---------------------------------------------------------------------------
__global__ __launch_bounds__(256)
void prep_qk(const float* __restrict__ temp) {
    __shared__ __nv_bfloat16 sh[64 * BST];
    __shared__ __nv_bfloat16 sl[64 * BST];
    int bid = blockIdx.x;
    int tsel = bid & 1, jc = (bid >> 1) & 7, unit = bid >> 4;
    int h = unit & 7, ww = (unit >> 3) & 7, b = unit >> 6;
    const float* src = temp + (size_t)tsel * PLANE_ALL + ((size_t)b * CDIM + h * HD) * 4096;
    float scale = tsel ? 1.f : 0.125f;

    int t = threadIdx.x, lane = t & 31, w = t >> 5;
    int j = w * 8 + (lane & 7);
    int jg = jc * 64 + j;
    int sp = (jg >> 3) * 64 + ww * 8 + (jg & 7);
    const float* col = src + sp;

    #pragma unroll
    for (int it = 0; it < 8; it++) {
        int d = (it * 4 + (lane >> 3)) * 2;
        float a = scale * col[(size_t)d * 4096];
        float c = scale * col[(size_t)(d + 1) * 4096];
        __nv_bfloat16 ah, al, ch, cl;
        split1(a, ah, al); split1(c, ch, cl);
        *(uint32_t*)((char*)sh + j * 144 + d * 2) = packbf(ah, ch);
        *(uint32_t*)((char*)sl + j * 144 + d * 2) = packbf(al, cl);
    }
    __syncthreads();

    __nv_bfloat16* dh = (tsel ? g_kh : g_qh) + (size_t)unit * 32768 + jc * 4096;
    __nv_bfloat16* dl = (tsel ? g_kl : g_ql) + (size_t)unit * 32768 + jc * 4096;
    int seg = lane & 7, r4 = lane >> 3;
    #pragma unroll
    for (int it = 0; it < 2; it++) {
        int r = w * 8 + it * 4 + r4;
        *(uint4*)((char*)(dh + r * 64) + seg * 16) = *(uint4*)((char*)sh + r * 144 + seg * 16);
        *(uint4*)((char*)(dl + r * 64) + seg * 16) = *(uint4*)((char*)sl + r * 144 + seg * 16);
    }
}

// ---------------------------------------------------------------------------
// Pre-pass 2: V -> bf16 hi/lo scratch [unit][d][j]
// ---------------------------------------------------------------------------
__global__ __launch_bounds__(256)
void prep_v(const float* __restrict__ temp) {
    int bid = blockIdx.x;
    int unit = bid >> 2, d0 = (bid & 3) * 16;
    int h = unit & 7, ww = (unit >> 3) & 7, b = unit >> 6;
    const float* vb = temp + 2 * PLANE_ALL + ((size_t)b * CDIM + h * HD) * 4096;
    int t = threadIdx.x;
    #pragma unroll
    for (int it = 0; it < 16; it++) {
        int pid = it * 256 + t;
        int j = (pid & 255) * 2;
        int d = d0 + (pid >> 8);
        int sp = (j >> 3) * 64 + ww * 8 + (j & 7);
        float2 x = *(const float2*)&vb[(size_t)d * 4096 + sp];
        __nv_bfloat16 ah, al, ch, cl;
        split1(x.x, ah, al); split1(x.y, ch, cl);
        size_t o = (size_t)unit * 32768 + d * 512 + j;
        *(uint32_t*)&g_vh[o] = packbf(ah, ch);
        *(uint32_t*)&g_vl[o] = packbf(al, cl);
    }
}

// ---------------------------------------------------------------------------
// Kernel A: depthwise 3x3 conv (lepe) -> writes base output layer
// ---------------------------------------------------------------------------
__global__ __launch_bounds__(256)
void lepe_kernel(const float* __restrict__ v, const float* __restrict__ cw,
                 const float* __restrict__ cb, float* __restrict__ out) {
    extern __shared__ float sm[];
    float* vs = sm;
    float* ws = vs + 64 * 195;
    float* bs = ws + 576;

    int bx = blockIdx.x;
    int b = bx >> 6, row = bx & 63;
    int c0 = blockIdx.y * 64;
    int t = threadIdx.x;

    for (int idx = t; idx < 64 * 3 * 64; idx += 256) {
        int c = idx / 192, rem = idx - c * 192;
        int r = rem >> 6, col = rem & 63;
        int gr = row + r - 1;
        float val = 0.f;
        if (gr >= 0 && gr < 64)
            val = v[(((size_t)b * CDIM + c0 + c) * 64 + gr) * 64 + col];
        vs[c * 195 + r * 65 + col] = val;
    }
    for (int idx = t; idx < 576; idx += 256) ws[idx] = cw[(size_t)c0 * 9 + idx];
    if (t < 64) bs[t] = cb[c0 + t];
    __syncthreads();

    int c = t & 63, cg = t >> 6;
    float w0 = ws[c*9+0], w1 = ws[c*9+1], w2 = ws[c*9+2];
    float w3 = ws[c*9+3], w4 = ws[c*9+4], w5 = ws[c*9+5];
    float w6 = ws[c*9+6], w7 = ws[c*9+7], w8 = ws[c*9+8];
    float bias = bs[c];
    const float* base = &vs[c * 195];

    #pragma unroll
    for (int it = 0; it < 16; it++) {
        int col = it * 4 + cg;
        float l0 = (col > 0)  ? base[0*65 + col - 1] : 0.f;
        float l1 = (col > 0)  ? base[1*65 + col - 1] : 0.f;
        float l2 = (col > 0)  ? base[2*65 + col - 1] : 0.f;
        float m0 = base[0*65 + col], m1 = base[1*65 + col], m2 = base[2*65 + col];
        float r0 = (col < 63) ? base[0*65 + col + 1] : 0.f;
        float r1 = (col < 63) ? base[1*65 + col + 1] : 0.f;
        float r2 = (col < 63) ? base[2*65 + col + 1] : 0.f;
        float sum = bias;
        sum += l0*w0 + m0*w1 + r0*w2;
        sum += l1*w3 + m1*w4 + r1*w5;
        sum += l2*w6 + m2*w7 + r2*w8;
        out[((size_t)b * 4096 + row * 64 + col) * CDIM + c0 + c] = sum;
    }
}

// ---------------------------------------------------------------------------
// Kernel B: attention. Phase1 2m x 4n (Q in regs, B redundancy 2x), S stored
// fragment-linear in global; Phase2 rebuilds P A-frags via coalesced LDG +
// in-register activation (no P smem). grid 4096, 256 threads, 2 CTAs/SM.
// ---------------------------------------------------------------------------
__global__ __launch_bounds__(256, 2)
void attn_mma_kernel(const float* __restrict__ polar, float* __restrict__ out) {
    extern __shared__ char smc[];
    const uint32_t sb = smem_u32(smc);
    float* phiA = (float*)(smc + OFF_PHI);
    float* riA  = (float*)(smc + OFF_RI);
    float* sum2 = (float*)(smc + OFF_SUM2);

    int t = threadIdx.x;
    int bid = blockIdx.x;
    int rb = bid & 7;
    int unit = bid >> 3;
    int ww = (unit >> 3) & 7, b = unit >> 6;

    int lane = t & 31, wid = t >> 5;
    int g = lane >> 2, tg = lane & 3;

    // phase-1 roles: 2 m-groups x 4 n-quarters
    int mg = wid >> 2, nq = wid & 3;
    // phase-2 / epilogue roles: 4 m-tiles x 2 n-halves
    int mt2 = wid >> 1;
    int nb = (wid & 1) * 32;

    float4* Sg4 = (float4*)(g_S + (size_t)bid * 32768);

    // ldmatrix lane roles
    int lrow = lane & 7, lsel = lane >> 3;
    uint32_t b_off1 = (uint32_t)((nq * 16 + lrow) * 144 + lsel * 16);   // phase1 B
    uint32_t b_off2 = (uint32_t)((nb + lrow) * 144 + lsel * 16);        // phase2 B

    const __nv_bfloat16* qh = g_qh + (size_t)unit * 32768 + rb * 4096;
    const __nv_bfloat16* ql = g_ql + (size_t)unit * 32768 + rb * 4096;
    const __nv_bfloat16* kh = g_kh + (size_t)unit * 32768;
    const __nv_bfloat16* kl = g_kl + (size_t)unit * 32768;
    const __nv_bfloat16* vh = g_vh + (size_t)unit * 32768;
    const __nv_bfloat16* vl = g_vl + (size_t)unit * 32768;

    int crow = t >> 3, cseg = t & 7;
    #define CPY64(dstoff, srcp, rstride) do {                                   \
        _Pragma("unroll")                                                       \
        for (int k_ = 0; k_ < 2; k_++) {                                        \
            int row_ = crow + k_ * 32;                                          \
            CP16(sb + (dstoff) + row_ * 144 + cseg * 16,                        \
                 (const char*)((srcp) + (size_t)row_ * (rstride)) + cseg * 16); \
        }                                                                       \
    } while (0)

    // prologue: G0 = Q + K0
    CPY64(OFF_QH, qh, 64);
    CPY64(OFF_QL, ql, 64);
    CPY64(OFF_K0H, kh, 64);
    CPY64(OFF_K0H + 9216, kl, 64);
    CPCOMMIT();

    // phi
    for (int s = t; s < 512; s += 256) {
        int rp = s >> 3, cp = ww * 8 + (s & 7);
        phiA[s] = polar[(((size_t)b * 64 + rp) * 64 + cp) * 2 + 1];
    }

    // G1 = K1
    CPY64(OFF_K0H + 18432, kh + 4096, 64);
    CPY64(OFF_K0H + 18432 + 9216, kl + 4096, 64);
    CPCOMMIT();

    CPWAIT1();            // G0 done: Q + K0 ready
    __syncthreads();

    // ---- Q fragments -> registers (m32 per warp: 2 m-tiles) ----
    uint32_t aqh[2][4][4], aql[2][4][4];
    #pragma unroll
    for (int mt = 0; mt < 2; mt++) {
        uint32_t a_off1 = (uint32_t)((mg * 32 + mt * 16 + (lsel & 1) * 8 + lrow) * 144
                                     + (lsel >> 1) * 16);
        #pragma unroll
        for (int kt = 0; kt < 4; kt++) {
            ldsm_x4(aqh[mt][kt][0], aqh[mt][kt][1], aqh[mt][kt][2], aqh[mt][kt][3],
                    sb + OFF_QH + a_off1 + kt * 32);
            ldsm_x4(aql[mt][kt][0], aql[mt][kt][1], aql[mt][kt][2], aql[mt][kt][3],
                    sb + OFF_QL + a_off1 + kt * 32);
        }
    }

    float phq0[2], phq1[2];
    #pragma unroll
    for (int mt = 0; mt < 2; mt++) {
        phq0[mt] = phiA[rb * 64 + mg * 32 + mt * 16 + g];
        phq1[mt] = phiA[rb * 64 + mg * 32 + mt * 16 + g + 8];
    }
    float rs[4] = {0.f, 0.f, 0.f, 0.f};   // [mt*2 + rowhalf]

    // ---- Phase 1: S = Qs @ K^T + rpe -> fragment-linear global S ----
    for (int jc = 0; jc < 8; jc++) {
        uint32_t kbase = OFF_K0H + (uint32_t)(jc & 1) * 18432;

        uint32_t bkh[2][2][4];
        #pragma unroll
        for (int kt2 = 0; kt2 < 2; kt2++)
            #pragma unroll
            for (int nt = 0; nt < 2; nt++)
                ldsm_x4(bkh[kt2][nt][0], bkh[kt2][nt][1], bkh[kt2][nt][2], bkh[kt2][nt][3],
                        sb + kbase + b_off1 + nt * 1152 + kt2 * 64);

        float acc[2][2][4];
        #pragma unroll
        for (int mt = 0; mt < 2; mt++)
            #pragma unroll
            for (int nt = 0; nt < 2; nt++)
                #pragma unroll
                for (int e = 0; e < 4; e++) acc[mt][nt][e] = 0.f;

        // term 0: QH x KH
        #pragma unroll
        for (int kt2 = 0; kt2 < 2; kt2++)
            #pragma unroll
            for (int mt = 0; mt < 2; mt++)
                #pragma unroll
                for (int nt = 0; nt < 2; nt++) {
                    mma16816(acc[mt][nt], aqh[mt][2*kt2][0], aqh[mt][2*kt2][1],
                             aqh[mt][2*kt2][2], aqh[mt][2*kt2][3],
                             bkh[kt2][nt][0], bkh[kt2][nt][1]);
                    mma16816(acc[mt][nt], aqh[mt][2*kt2+1][0], aqh[mt][2*kt2+1][1],
                             aqh[mt][2*kt2+1][2], aqh[mt][2*kt2+1][3],
                             bkh[kt2][nt][2], bkh[kt2][nt][3]);
                }
        // term 1: QH x KL (streamed)
        #pragma unroll
        for (int kt2 = 0; kt2 < 2; kt2++)
            #pragma unroll
            for (int nt = 0; nt < 2; nt++) {
                uint32_t t0, t1, t2, t3;
                ldsm_x4(t0, t1, t2, t3,
                        sb + kbase + 9216 + b_off1 + nt * 1152 + kt2 * 64);
                #pragma unroll
                for (int mt = 0; mt < 2; mt++) {
                    mma16816(acc[mt][nt], aqh[mt][2*kt2][0], aqh[mt][2*kt2][1],
                             aqh[mt][2*kt2][2], aqh[mt][2*kt2][3], t0, t1);
                    mma16816(acc[mt][nt], aqh[mt][2*kt2+1][0], aqh[mt][2*kt2+1][1],
                             aqh[mt][2*kt2+1][2], aqh[mt][2*kt2+1][3], t2, t3);
                }
            }
        // term 2: QL x KH
        #pragma unroll
        for (int kt2 = 0; kt2 < 2; kt2++)
            #pragma unroll
            for (int mt = 0; mt < 2; mt++)
                #pragma unroll
                for (int nt = 0; nt < 2; nt++) {
                    mma16816(acc[mt][nt], aql[mt][2*kt2][0], aql[mt][2*kt2][1],
                             aql[mt][2*kt2][2], aql[mt][2*kt2][3],
                             bkh[kt2][nt][0], bkh[kt2][nt][1]);
                    mma16816(acc[mt][nt], aql[mt][2*kt2+1][0], aql[mt][2*kt2+1][1],
                             aql[mt][2*kt2+1][2], aql[mt][2*kt2+1][3],
                             bkh[kt2][nt][2], bkh[kt2][nt][3]);
                }

        // fold rpe, accumulate row L1 partials, store fragment unit (coalesced)
        #pragma unroll
        for (int mt = 0; mt < 2; mt++)
            #pragma unroll
            for (int nt = 0; nt < 2; nt++) {
                int colj = jc * 64 + nq * 16 + nt * 8 + tg * 2;
                float2 pk = *(const float2*)&phiA[colj];
                float s0 = acc[mt][nt][0] + phq0[mt] - pk.x;
                float s1 = acc[mt][nt][1] + phq0[mt] - pk.y;
                float s2 = acc[mt][nt][2] + phq1[mt] - pk.x;
                float s3 = acc[mt][nt][3] + phq1[mt] - pk.y;
                rs[mt * 2 + 0] += fabsf(s0) + fabsf(s1);
                rs[mt * 2 + 1] += fabsf(s2) + fabsf(s3);
                int MT = mg * 2 + mt;
                int CT = jc * 8 + nq * 2 + nt;
                Sg4[(MT * 64 + CT) * 32 + lane] = make_float4(s0, s1, s2, s3);
            }

        __syncthreads();                         // K chunk jc consumed
        if (jc < 6) {
            uint32_t bo = OFF_K0H + (uint32_t)(jc & 1) * 18432;
            CPY64(bo, kh + (jc + 2) * 4096, 64);
            CPY64(bo + 9216, kl + (jc + 2) * 4096, 64);
            CPCOMMIT();
        } else if (jc == 6) {                     // prefetch V0 into buf 0
            CPY64(OFF_K0H, vh, 512);
            CPY64(OFF_K0H + 9216, vl, 512);
            CPCOMMIT();
        }
        if (jc < 7) {
            CPWAIT1();
            __syncthreads();
        }
    }

    // ---- row L1 -> ri ----
    #pragma unroll
    for (int i = 0; i < 4; i++) {
        rs[i] += __shfl_xor_sync(0xffffffffu, rs[i], 1);
        rs[i] += __shfl_xor_sync(0xffffffffu, rs[i], 2);
    }
    if (tg == 0) {
        #pragma unroll
        for (int mt = 0; mt < 2; mt++) {
            int r0 = mg * 32 + mt * 16 + g;
            sum2[r0 * 4 + nq]       = rs[mt * 2 + 0];
            sum2[(r0 + 8) * 4 + nq] = rs[mt * 2 + 1];
        }
    }
    __syncthreads();
    if (t < 64)
        riA[t] = 1.5707963267948966f /
                 (sum2[t*4] + sum2[t*4+1] + sum2[t*4+2] + sum2[t*4+3] + 1e-8f);
    __syncthreads();

    // ---- Phase 2: A-frags from fragment-linear S (coalesced LDG) + act ----
    float oacc[4][4];
    #pragma unroll
    for (int nt = 0; nt < 4; nt++)
        #pragma unroll
        for (int e = 0; e < 4; e++) oacc[nt][e] = 0.f;

    float ri_a = riA[mt2 * 16 + g];
    float ri_b = riA[mt2 * 16 + g + 8];

    for (int jc = 0; jc < 8; jc++) {
        if (jc < 7) {
            uint32_t bo = OFF_K0H + (uint32_t)((jc + 1) & 1) * 18432;
            CPY64(bo, vh + (jc + 1) * 64, 512);
            CPY64(bo + 9216, vl + (jc + 1) * 64, 512);
            CPCOMMIT();
        }
        // build P A-fragments in registers (overlaps async copy)
        uint32_t aph[4][4], apl[4][4];
        #pragma unroll
        for (int kt = 0; kt < 4; kt++) {
            float4 u = Sg4[(mt2 * 64 + jc * 8 + 2 * kt) * 32 + lane];
            float4 w = Sg4[(mt2 * 64 + jc * 8 + 2 * kt + 1) * 32 + lane];
            float p0 = act1(u.x, ri_a), p1 = act1(u.y, ri_a);
            float p2 = act1(u.z, ri_b), p3 = act1(u.w, ri_b);
            float p4 = act1(w.x, ri_a), p5 = act1(w.y, ri_a);
            float p6 = act1(w.z, ri_b), p7 = act1(w.w, ri_b);
            __nv_bfloat16 h0,l0,h1,l1,h2,l2,h3,l3,h4,l4,h5,l5,h6,l6,h7,l7;
            split1(p0,h0,l0); split1(p1,h1,l1); split1(p2,h2,l2); split1(p3,h3,l3);
            split1(p4,h4,l4); split1(p5,h5,l5); split1(p6,h6,l6); split1(p7,h7,l7);
            aph[kt][0] = packbf(h0,h1); apl[kt][0] = packbf(l0,l1);
            aph[kt][1] = packbf(h2,h3); apl[kt][1] = packbf(l2,l3);
            aph[kt][2] = packbf(h4,h5); apl[kt][2] = packbf(l4,l5);
            aph[kt][3] = packbf(h6,h7); apl[kt][3] = packbf(l6,l7);
        }
        if (jc < 7) { CPWAIT1(); } else { CPWAIT0(); }
        __syncthreads();                          // V chunk jc ready

        uint32_t vbase = OFF_K0H + (uint32_t)(jc & 1) * 18432;

        uint32_t bvh[2][4][4];
        #pragma unroll
        for (int kt2 = 0; kt2 < 2; kt2++)
            #pragma unroll
            for (int nt = 0; nt < 4; nt++)
                ldsm_x4(bvh[kt2][nt][0], bvh[kt2][nt][1], bvh[kt2][nt][2], bvh[kt2][nt][3],
                        sb + vbase + b_off2 + nt * 1152 + kt2 * 64);

        // term 0: PH x VH
        #pragma unroll
        for (int kt2 = 0; kt2 < 2; kt2++)
            #pragma unroll
            for (int nt = 0; nt < 4; nt++) {
                mma16816(oacc[nt], aph[2*kt2][0], aph[2*kt2][1], aph[2*kt2][2], aph[2*kt2][3],
                         bvh[kt2][nt][0], bvh[kt2][nt][1]);
                mma16816(oacc[nt], aph[2*kt2+1][0], aph[2*kt2+1][1], aph[2*kt2+1][2], aph[2*kt2+1][3],
                         bvh[kt2][nt][2], bvh[kt2][nt][3]);
            }
        // term 1: PH x VL (streamed)
        #pragma unroll
        for (int kt2 = 0; kt2 < 2; kt2++)
            #pragma unroll
            for (int nt = 0; nt < 4; nt++) {
                uint32_t t0, t1, t2, t3;
                ldsm_x4(t0, t1, t2, t3,
                        sb + vbase + 9216 + b_off2 + nt * 1152 + kt2 * 64);
                mma16816(oacc[nt], aph[2*kt2][0], aph[2*kt2][1], aph[2*kt2][2], aph[2*kt2][3], t0, t1);
                mma16816(oacc[nt], aph[2*kt2+1][0], aph[2*kt2+1][1], aph[2*kt2+1][2], aph[2*kt2+1][3], t2, t3);
            }
        // term 2: PL x VH
        #pragma unroll
        for (int kt2 = 0; kt2 < 2; kt2++)
            #pragma unroll
            for (int nt = 0; nt < 4; nt++) {
                mma16816(oacc[nt], apl[2*kt2][0], apl[2*kt2][1], apl[2*kt2][2], apl[2*kt2][3],
                         bvh[kt2][nt][0], bvh[kt2][nt][1]);
                mma16816(oacc[nt], apl[2*kt2+1][0], apl[2*kt2+1][1], apl[2*kt2+1][2], apl[2*kt2+1][3],
                         bvh[kt2][nt][2], bvh[kt2][nt][3]);
            }

        __syncthreads();                          // before next V overwrite
    }

    // ---- Epilogue: RMW into out (lepe base already written) ----
    {
        int h = unit & 7;
        int sg0 = rb * 64 + mt2 * 16 + g;
        int sg1 = sg0 + 8;
        int sp0 = (sg0 >> 3) * 64 + ww * 8 + (sg0 & 7);
        int sp1 = (sg1 >> 3) * 64 + ww * 8 + (sg1 & 7);
        float* o0 = out + ((size_t)b * 4096 + sp0) * CDIM + h * HD;
        float* o1 = out + ((size_t)b * 4096 + sp1) * CDIM + h * HD;
        #pragma unroll
        for (int nt = 0; nt < 4; nt++) {
            int d0 = nb + nt * 8 + tg * 2;
            float2 c0 = *(float2*)&o0[d0];
            c0.x += oacc[nt][0]; c0.y += oacc[nt][1];
            *(float2*)&o0[d0] = c0;
            float2 c1 = *(float2*)&o1[d0];
            c1.x += oacc[nt][2]; c1.y += oacc[nt][3];
            *(float2*)&o1[d0] = c1;
        }
    }
}

// ---------------------------------------------------------------------------
extern "C" void kernel_launch(void* const* d_in, const int* in_sizes, int n_in,
                              void* d_out, int out_size) {
    const float* temp  = (const float*)d_in[0];  // [3, 8, 512, 64, 64]
    const float* polar = (const float*)d_in[1];  // [8, 64, 64, 2]
    const float* cw    = (const float*)d_in[2];  // [512, 1, 3, 3]
    const float* cb    = (const float*)d_in[3];  // [512]
    float* out = (float*)d_out;                  // [8, 4096, 512]

    const float* v = temp + 2 * PLANE_ALL;

    size_t smA = (size_t)(64 * 195 + 576 + 64) * sizeof(float);
    cudaFuncSetAttribute(lepe_kernel, cudaFuncAttributeMaxDynamicSharedMemorySize, (int)smA);
    cudaFuncSetAttribute(attn_mma_kernel, cudaFuncAttributeMaxDynamicSharedMemorySize, SMEM_ATTN);

    prep_qk<<<UNITS * 16, 256>>>(temp);
    prep_v<<<UNITS * 4, 256>>>(temp);

    dim3 gA(BATCH * 64, CDIM / 64);
    lepe_kernel<<<gA, 256, smA>>>(v, cw, cb, out);
    attn_mma_kernel<<<4096, 256, SMEM_ATTN>>>(polar, out);
}

// round 13
// speedup vs baseline: 3.0196x; 1.0091x over previous
#include <cuda_runtime.h>
#include <cuda_bf16.h>
#include <stdint.h>
#include <math.h>

#define BATCH   8
#define CDIM    512
#define HD      64
#define UNITS   512
#define PLANE_ALL ((size_t)BATCH * CDIM * 64 * 64)

// ---- bf16 hi/lo scratch in operand layouts ----
// Q/K: [unit][token 512][d 64]  (128B rows)   V: [unit][d 64][j 512]
__device__ __nv_bfloat16 g_qh[(size_t)UNITS * 32768];
__device__ __nv_bfloat16 g_ql[(size_t)UNITS * 32768];
__device__ __nv_bfloat16 g_kh[(size_t)UNITS * 32768];
__device__ __nv_bfloat16 g_kl[(size_t)UNITS * 32768];
__device__ __nv_bfloat16 g_vh[(size_t)UNITS * 32768];
__device__ __nv_bfloat16 g_vl[(size_t)UNITS * 32768];
// S scratch, FRAGMENT-LINEAR: [cta][MT 4][CT 64][lane 32] x float4
__device__ float g_S[(size_t)4096 * 32768];

// ---- attn smem byte offsets ----
// K chunk: 128 rows x 144B per half (hi @ +0, lo @ +18432)
// V chunk: 64 rows x 272B per half (hi @ +0, lo @ +18432)
#define OFF_QH   0
#define OFF_QL   9216
#define OFF_B0   18432
#define BUFSTRIDE 36864
#define OFF_PHI  92160     /* 512 f32 */
#define OFF_RI   94208     /* 64 f32 */
#define OFF_SUM2 94464     /* 256 f32 */
#define SMEM_ATTN 95488

#define BST 72      /* bf16 row stride (144B) */

__device__ __forceinline__ void split1(float x, __nv_bfloat16& h, __nv_bfloat16& l) {
    h = __float2bfloat16(x);
    l = __float2bfloat16(x - __bfloat162float(h));
}
__device__ __forceinline__ uint32_t packbf(__nv_bfloat16 a, __nv_bfloat16 c) {
    return (uint32_t)__bfloat16_as_ushort(a) | ((uint32_t)__bfloat16_as_ushort(c) << 16);
}
__device__ __forceinline__ uint32_t smem_u32(const void* p) {
    uint32_t a;
    asm("{ .reg .u64 t; cvta.to.shared.u64 t, %1; cvt.u32.u64 %0, t; }" : "=r"(a) : "l"(p));
    return a;
}
__device__ __forceinline__ void mma16816(float* c, uint32_t a0, uint32_t a1,
                                         uint32_t a2, uint32_t a3,
                                         uint32_t b0, uint32_t b1) {
    asm volatile(
        "mma.sync.aligned.m16n8k16.row.col.f32.bf16.bf16.f32 "
        "{%0,%1,%2,%3}, {%4,%5,%6,%7}, {%8,%9}, {%0,%1,%2,%3};"
        : "+f"(c[0]), "+f"(c[1]), "+f"(c[2]), "+f"(c[3])
        : "r"(a0), "r"(a1), "r"(a2), "r"(a3), "r"(b0), "r"(b1));
}
__device__ __forceinline__ void ldsm_x4(uint32_t& r0, uint32_t& r1, uint32_t& r2,
                                        uint32_t& r3, uint32_t addr) {
    asm volatile("ldmatrix.sync.aligned.m8n8.x4.shared.b16 {%0,%1,%2,%3}, [%4];"
                 : "=r"(r0), "=r"(r1), "=r"(r2), "=r"(r3) : "r"(addr));
}
#define CP16(d, s)  asm volatile("cp.async.cg.shared.global [%0], [%1], 16;" :: "r"(d), "l"(s))
#define CPCOMMIT()  asm volatile("cp.async.commit_group;" ::: "memory")
#define CPWAIT1()   asm volatile("cp.async.wait_group 1;" ::: "memory")
#define CPWAIT0()   asm volatile("cp.async.wait_group 0;" ::: "memory")

__device__ __forceinline__ float act1(float s, float ri) {
    const float K1 =  0.5f;
    const float K2 = -1.f / 24.f;
    const float K3 =  1.f / 720.f;
    const float K4 = -1.f / 40320.f;
    const float K5 =  1.f / 3628800.f;
    const float K6 = -1.f / 479001600.f;
    float x = s * ri;
    float z = x * x;
    float p = fmaf(z, K6, K5);
    p = fmaf(z, p, K4);
    p = fmaf(z, p, K3);
    p = fmaf(z, p, K2);
    p = fmaf(z, p, K1);
    return z * p;
}

// ---------------------------------------------------------------------------
// Pre-pass 1: Q (scaled) and K -> bf16 hi/lo scratch [unit][token][d]
// ---------------------------------------------------------------------------
__global__ __launch_bounds__(256)
void prep_qk(const float* __restrict__ temp) {
    __shared__ __nv_bfloat16 sh[64 * BST];
    __shared__ __nv_bfloat16 sl[64 * BST];
    int bid = blockIdx.x;
    int tsel = bid & 1, jc = (bid >> 1) & 7, unit = bid >> 4;
    int h = unit & 7, ww = (unit >> 3) & 7, b = unit >> 6;
    const float* src = temp + (size_t)tsel * PLANE_ALL + ((size_t)b * CDIM + h * HD) * 4096;
    float scale = tsel ? 1.f : 0.125f;

    int t = threadIdx.x, lane = t & 31, w = t >> 5;
    int j = w * 8 + (lane & 7);
    int jg = jc * 64 + j;
    int sp = (jg >> 3) * 64 + ww * 8 + (jg & 7);
    const float* col = src + sp;

    #pragma unroll
    for (int it = 0; it < 8; it++) {
        int d = (it * 4 + (lane >> 3)) * 2;
        float a = scale * col[(size_t)d * 4096];
        float c = scale * col[(size_t)(d + 1) * 4096];
        __nv_bfloat16 ah, al, ch, cl;
        split1(a, ah, al); split1(c, ch, cl);
        *(uint32_t*)((char*)sh + j * 144 + d * 2) = packbf(ah, ch);
        *(uint32_t*)((char*)sl + j * 144 + d * 2) = packbf(al, cl);
    }
    __syncthreads();

    __nv_bfloat16* dh = (tsel ? g_kh : g_qh) + (size_t)unit * 32768 + jc * 4096;
    __nv_bfloat16* dl = (tsel ? g_kl : g_ql) + (size_t)unit * 32768 + jc * 4096;
    int seg = lane & 7, r4 = lane >> 3;
    #pragma unroll
    for (int it = 0; it < 2; it++) {
        int r = w * 8 + it * 4 + r4;
        *(uint4*)((char*)(dh + r * 64) + seg * 16) = *(uint4*)((char*)sh + r * 144 + seg * 16);
        *(uint4*)((char*)(dl + r * 64) + seg * 16) = *(uint4*)((char*)sl + r * 144 + seg * 16);
    }
}

// ---------------------------------------------------------------------------
// Pre-pass 2: V -> bf16 hi/lo scratch [unit][d][j]
// ---------------------------------------------------------------------------
__global__ __launch_bounds__(256)
void prep_v(const float* __restrict__ temp) {
    int bid = blockIdx.x;
    int unit = bid >> 2, d0 = (bid & 3) * 16;
    int h = unit & 7, ww = (unit >> 3) & 7, b = unit >> 6;
    const float* vb = temp + 2 * PLANE_ALL + ((size_t)b * CDIM + h * HD) * 4096;
    int t = threadIdx.x;
    #pragma unroll
    for (int it = 0; it < 16; it++) {
        int pid = it * 256 + t;
        int j = (pid & 255) * 2;
        int d = d0 + (pid >> 8);
        int sp = (j >> 3) * 64 + ww * 8 + (j & 7);
        float2 x = *(const float2*)&vb[(size_t)d * 4096 + sp];
        __nv_bfloat16 ah, al, ch, cl;
        split1(x.x, ah, al); split1(x.y, ch, cl);
        size_t o = (size_t)unit * 32768 + d * 512 + j;
        *(uint32_t*)&g_vh[o] = packbf(ah, ch);
        *(uint32_t*)&g_vl[o] = packbf(al, cl);
    }
}

// ---------------------------------------------------------------------------
// Kernel A: depthwise 3x3 conv (lepe) -> writes base output layer
// ---------------------------------------------------------------------------
__global__ __launch_bounds__(256)
void lepe_kernel(const float* __restrict__ v, const float* __restrict__ cw,
                 const float* __restrict__ cb, float* __restrict__ out) {
    extern __shared__ float sm[];
    float* vs = sm;
    float* ws = vs + 64 * 195;
    float* bs = ws + 576;

    int bx = blockIdx.x;
    int b = bx >> 6, row = bx & 63;
    int c0 = blockIdx.y * 64;
    int t = threadIdx.x;

    for (int idx = t; idx < 64 * 3 * 64; idx += 256) {
        int c = idx / 192, rem = idx - c * 192;
        int r = rem >> 6, col = rem & 63;
        int gr = row + r - 1;
        float val = 0.f;
        if (gr >= 0 && gr < 64)
            val = v[(((size_t)b * CDIM + c0 + c) * 64 + gr) * 64 + col];
        vs[c * 195 + r * 65 + col] = val;
    }
    for (int idx = t; idx < 576; idx += 256) ws[idx] = cw[(size_t)c0 * 9 + idx];
    if (t < 64) bs[t] = cb[c0 + t];
    __syncthreads();

    int c = t & 63, cg = t >> 6;
    float w0 = ws[c*9+0], w1 = ws[c*9+1], w2 = ws[c*9+2];
    float w3 = ws[c*9+3], w4 = ws[c*9+4], w5 = ws[c*9+5];
    float w6 = ws[c*9+6], w7 = ws[c*9+7], w8 = ws[c*9+8];
    float bias = bs[c];
    const float* base = &vs[c * 195];

    #pragma unroll
    for (int it = 0; it < 16; it++) {
        int col = it * 4 + cg;
        float l0 = (col > 0)  ? base[0*65 + col - 1] : 0.f;
        float l1 = (col > 0)  ? base[1*65 + col - 1] : 0.f;
        float l2 = (col > 0)  ? base[2*65 + col - 1] : 0.f;
        float m0 = base[0*65 + col], m1 = base[1*65 + col], m2 = base[2*65 + col];
        float r0 = (col < 63) ? base[0*65 + col + 1] : 0.f;
        float r1 = (col < 63) ? base[1*65 + col + 1] : 0.f;
        float r2 = (col < 63) ? base[2*65 + col + 1] : 0.f;
        float sum = bias;
        sum += l0*w0 + m0*w1 + r0*w2;
        sum += l1*w3 + m1*w4 + r1*w5;
        sum += l2*w6 + m2*w7 + r2*w8;
        out[((size_t)b * 4096 + row * 64 + col) * CDIM + c0 + c] = sum;
    }
}

// ---------------------------------------------------------------------------
// Kernel B: attention, 128-col chunks (4 iters/phase), halved syncs.
// Phase1: 2m x 4n per n-half; Phase2: P frags from fragment-linear S.
// grid 4096, 256 threads, 2 CTAs/SM.
// ---------------------------------------------------------------------------
__global__ __launch_bounds__(256, 2)
void attn_mma_kernel(const float* __restrict__ polar, float* __restrict__ out) {
    extern __shared__ char smc[];
    const uint32_t sb = smem_u32(smc);
    float* phiA = (float*)(smc + OFF_PHI);
    float* riA  = (float*)(smc + OFF_RI);
    float* sum2 = (float*)(smc + OFF_SUM2);

    int t = threadIdx.x;
    int bid = blockIdx.x;
    int rb = bid & 7;
    int unit = bid >> 3;
    int ww = (unit >> 3) & 7, b = unit >> 6;

    int lane = t & 31, wid = t >> 5;
    int g = lane >> 2, tg = lane & 3;

    int mg = wid >> 2, nq = wid & 3;       // phase-1 roles
    int mt2 = wid >> 1;                    // phase-2 / epilogue roles
    int nb = (wid & 1) * 32;

    float4* Sg4 = (float4*)(g_S + (size_t)bid * 32768);

    int lrow = lane & 7, lsel = lane >> 3;
    uint32_t b_off1 = (uint32_t)((nq * 16 + lrow) * 144 + lsel * 16);   // phase1 K B
    uint32_t b_off2 = (uint32_t)((nb + lrow) * 272 + lsel * 16);        // phase2 V B

    const __nv_bfloat16* qh = g_qh + (size_t)unit * 32768 + rb * 4096;
    const __nv_bfloat16* ql = g_ql + (size_t)unit * 32768 + rb * 4096;
    const __nv_bfloat16* kh = g_kh + (size_t)unit * 32768;
    const __nv_bfloat16* kl = g_kl + (size_t)unit * 32768;
    const __nv_bfloat16* vh = g_vh + (size_t)unit * 32768;
    const __nv_bfloat16* vl = g_vl + (size_t)unit * 32768;

    int crow = t >> 3, cseg = t & 7;
    // Q: 64 rows x 128B into 144B stride
    #define CPYQ(dstoff, srcp) do {                                             \
        _Pragma("unroll")                                                       \
        for (int k_ = 0; k_ < 2; k_++) {                                        \
            int row_ = crow + k_ * 32;                                          \
            CP16(sb + (dstoff) + row_ * 144 + cseg * 16,                        \
                 (const char*)((srcp) + (size_t)row_ * 64) + cseg * 16);        \
        }                                                                       \
    } while (0)
    // K chunk: 128 rows x 128B into 144B stride
    #define CPYK(dstoff, srcp) do {                                             \
        _Pragma("unroll")                                                       \
        for (int k_ = 0; k_ < 4; k_++) {                                        \
            int row_ = crow + k_ * 32;                                          \
            CP16(sb + (dstoff) + row_ * 144 + cseg * 16,                        \
                 (const char*)((srcp) + (size_t)row_ * 64) + cseg * 16);        \
        }                                                                       \
    } while (0)
    int vrow = t >> 4, vseg = t & 15;
    // V chunk: 64 rows x 256B into 272B stride (src row stride 512 elems)
    #define CPYV(dstoff, srcp) do {                                             \
        _Pragma("unroll")                                                       \
        for (int k_ = 0; k_ < 4; k_++) {                                        \
            int row_ = vrow + k_ * 16;                                          \
            CP16(sb + (dstoff) + row_ * 272 + vseg * 16,                        \
                 (const char*)((srcp) + (size_t)row_ * 512) + vseg * 16);       \
        }                                                                       \
    } while (0)

    // prologue: G0 = Q + K chunk0, G1 = K chunk1
    CPYQ(OFF_QH, qh);
    CPYQ(OFF_QL, ql);
    CPYK(OFF_B0, kh);
    CPYK(OFF_B0 + 18432, kl);
    CPCOMMIT();

    for (int s = t; s < 512; s += 256) {
        int rp = s >> 3, cp = ww * 8 + (s & 7);
        phiA[s] = polar[(((size_t)b * 64 + rp) * 64 + cp) * 2 + 1];
    }

    CPYK(OFF_B0 + BUFSTRIDE, kh + 8192);
    CPYK(OFF_B0 + BUFSTRIDE + 18432, kl + 8192);
    CPCOMMIT();

    CPWAIT1();
    __syncthreads();

    // ---- Q fragments -> registers ----
    uint32_t aqh[2][4][4], aql[2][4][4];
    #pragma unroll
    for (int mt = 0; mt < 2; mt++) {
        uint32_t a_off1 = (uint32_t)((mg * 32 + mt * 16 + (lsel & 1) * 8 + lrow) * 144
                                     + (lsel >> 1) * 16);
        #pragma unroll
        for (int kt = 0; kt < 4; kt++) {
            ldsm_x4(aqh[mt][kt][0], aqh[mt][kt][1], aqh[mt][kt][2], aqh[mt][kt][3],
                    sb + OFF_QH + a_off1 + kt * 32);
            ldsm_x4(aql[mt][kt][0], aql[mt][kt][1], aql[mt][kt][2], aql[mt][kt][3],
                    sb + OFF_QL + a_off1 + kt * 32);
        }
    }

    float phq0[2], phq1[2];
    #pragma unroll
    for (int mt = 0; mt < 2; mt++) {
        phq0[mt] = phiA[rb * 64 + mg * 32 + mt * 16 + g];
        phq1[mt] = phiA[rb * 64 + mg * 32 + mt * 16 + g + 8];
    }
    float rs[4] = {0.f, 0.f, 0.f, 0.f};

    // ---- Phase 1: 4 chunks of 128 cols, two n-halves each ----
    for (int jc = 0; jc < 4; jc++) {
        uint32_t kbase = OFF_B0 + (uint32_t)(jc & 1) * BUFSTRIDE;

        #pragma unroll
        for (int nh = 0; nh < 2; nh++) {
            uint32_t nbase = kbase + b_off1 + (uint32_t)nh * 9216;

            uint32_t bkh[2][2][4];
            #pragma unroll
            for (int kt2 = 0; kt2 < 2; kt2++)
                #pragma unroll
                for (int nt = 0; nt < 2; nt++)
                    ldsm_x4(bkh[kt2][nt][0], bkh[kt2][nt][1], bkh[kt2][nt][2], bkh[kt2][nt][3],
                            sb + nbase + nt * 1152 + kt2 * 64);

            float acc[2][2][4];
            #pragma unroll
            for (int mt = 0; mt < 2; mt++)
                #pragma unroll
                for (int nt = 0; nt < 2; nt++)
                    #pragma unroll
                    for (int e = 0; e < 4; e++) acc[mt][nt][e] = 0.f;

            // term 0: QH x KH
            #pragma unroll
            for (int kt2 = 0; kt2 < 2; kt2++)
                #pragma unroll
                for (int mt = 0; mt < 2; mt++)
                    #pragma unroll
                    for (int nt = 0; nt < 2; nt++) {
                        mma16816(acc[mt][nt], aqh[mt][2*kt2][0], aqh[mt][2*kt2][1],
                                 aqh[mt][2*kt2][2], aqh[mt][2*kt2][3],
                                 bkh[kt2][nt][0], bkh[kt2][nt][1]);
                        mma16816(acc[mt][nt], aqh[mt][2*kt2+1][0], aqh[mt][2*kt2+1][1],
                                 aqh[mt][2*kt2+1][2], aqh[mt][2*kt2+1][3],
                                 bkh[kt2][nt][2], bkh[kt2][nt][3]);
                    }
            // term 1: QH x KL (streamed)
            #pragma unroll
            for (int kt2 = 0; kt2 < 2; kt2++)
                #pragma unroll
                for (int nt = 0; nt < 2; nt++) {
                    uint32_t t0, t1, t2, t3;
                    ldsm_x4(t0, t1, t2, t3, sb + nbase + 18432 + nt * 1152 + kt2 * 64);
                    #pragma unroll
                    for (int mt = 0; mt < 2; mt++) {
                        mma16816(acc[mt][nt], aqh[mt][2*kt2][0], aqh[mt][2*kt2][1],
                                 aqh[mt][2*kt2][2], aqh[mt][2*kt2][3], t0, t1);
                        mma16816(acc[mt][nt], aqh[mt][2*kt2+1][0], aqh[mt][2*kt2+1][1],
                                 aqh[mt][2*kt2+1][2], aqh[mt][2*kt2+1][3], t2, t3);
                    }
                }
            // term 2: QL x KH
            #pragma unroll
            for (int kt2 = 0; kt2 < 2; kt2++)
                #pragma unroll
                for (int mt = 0; mt < 2; mt++)
                    #pragma unroll
                    for (int nt = 0; nt < 2; nt++) {
                        mma16816(acc[mt][nt], aql[mt][2*kt2][0], aql[mt][2*kt2][1],
                                 aql[mt][2*kt2][2], aql[mt][2*kt2][3],
                                 bkh[kt2][nt][0], bkh[kt2][nt][1]);
                        mma16816(acc[mt][nt], aql[mt][2*kt2+1][0], aql[mt][2*kt2+1][1],
                                 aql[mt][2*kt2+1][2], aql[mt][2*kt2+1][3],
                                 bkh[kt2][nt][2], bkh[kt2][nt][3]);
                    }

            // fold rpe, L1 partials, store fragment-linear
            #pragma unroll
            for (int mt = 0; mt < 2; mt++)
                #pragma unroll
                for (int nt = 0; nt < 2; nt++) {
                    int colj = jc * 128 + nh * 64 + nq * 16 + nt * 8 + tg * 2;
                    float2 pk = *(const float2*)&phiA[colj];
                    float s0 = acc[mt][nt][0] + phq0[mt] - pk.x;
                    float s1 = acc[mt][nt][1] + phq0[mt] - pk.y;
                    float s2 = acc[mt][nt][2] + phq1[mt] - pk.x;
                    float s3 = acc[mt][nt][3] + phq1[mt] - pk.y;
                    rs[mt * 2 + 0] += fabsf(s0) + fabsf(s1);
                    rs[mt * 2 + 1] += fabsf(s2) + fabsf(s3);
                    int MT = mg * 2 + mt;
                    int CT = jc * 16 + nh * 8 + nq * 2 + nt;
                    Sg4[(MT * 64 + CT) * 32 + lane] = make_float4(s0, s1, s2, s3);
                }
        }

        __syncthreads();                         // chunk jc consumed
        if (jc < 2) {
            uint32_t bo = OFF_B0 + (uint32_t)(jc & 1) * BUFSTRIDE;
            CPYK(bo, kh + (jc + 2) * 8192);
            CPYK(bo + 18432, kl + (jc + 2) * 8192);
            CPCOMMIT();
        } else if (jc == 2) {                     // prefetch V chunk0 into buf0
            CPYV(OFF_B0, vh);
            CPYV(OFF_B0 + 18432, vl);
            CPCOMMIT();
        }
        if (jc < 3) {
            CPWAIT1();
            __syncthreads();
        }
    }

    // ---- row L1 -> ri ----
    #pragma unroll
    for (int i = 0; i < 4; i++) {
        rs[i] += __shfl_xor_sync(0xffffffffu, rs[i], 1);
        rs[i] += __shfl_xor_sync(0xffffffffu, rs[i], 2);
    }
    if (tg == 0) {
        #pragma unroll
        for (int mt = 0; mt < 2; mt++) {
            int r0 = mg * 32 + mt * 16 + g;
            sum2[r0 * 4 + nq]       = rs[mt * 2 + 0];
            sum2[(r0 + 8) * 4 + nq] = rs[mt * 2 + 1];
        }
    }
    __syncthreads();
    if (t < 64)
        riA[t] = 1.5707963267948966f /
                 (sum2[t*4] + sum2[t*4+1] + sum2[t*4+2] + sum2[t*4+3] + 1e-8f);
    __syncthreads();

    // ---- Phase 2: 4 chunks of 128 k, two k-halves each ----
    float oacc[4][4];
    #pragma unroll
    for (int nt = 0; nt < 4; nt++)
        #pragma unroll
        for (int e = 0; e < 4; e++) oacc[nt][e] = 0.f;

    float ri_a = riA[mt2 * 16 + g];
    float ri_b = riA[mt2 * 16 + g + 8];

    for (int jc = 0; jc < 4; jc++) {
        if (jc < 3) {
            uint32_t bo = OFF_B0 + (uint32_t)((jc + 1) & 1) * BUFSTRIDE;
            CPYV(bo, vh + (jc + 1) * 128);
            CPYV(bo + 18432, vl + (jc + 1) * 128);
            CPCOMMIT();
        }
        uint32_t vbase = OFF_B0 + (uint32_t)(jc & 1) * BUFSTRIDE;

        #pragma unroll
        for (int kh2 = 0; kh2 < 2; kh2++) {
            // build P A-frags for this k-half (first one overlaps async copy)
            uint32_t aph[4][4], apl[4][4];
            #pragma unroll
            for (int kt = 0; kt < 4; kt++) {
                int CT = jc * 16 + kh2 * 8 + 2 * kt;
                float4 u = Sg4[(mt2 * 64 + CT) * 32 + lane];
                float4 w = Sg4[(mt2 * 64 + CT + 1) * 32 + lane];
                float p0 = act1(u.x, ri_a), p1 = act1(u.y, ri_a);
                float p2 = act1(u.z, ri_b), p3 = act1(u.w, ri_b);
                float p4 = act1(w.x, ri_a), p5 = act1(w.y, ri_a);
                float p6 = act1(w.z, ri_b), p7 = act1(w.w, ri_b);
                __nv_bfloat16 h0,l0,h1,l1,h2,l2,h3,l3,h4,l4,h5,l5,h6,l6,h7,l7;
                split1(p0,h0,l0); split1(p1,h1,l1); split1(p2,h2,l2); split1(p3,h3,l3);
                split1(p4,h4,l4); split1(p5,h5,l5); split1(p6,h6,l6); split1(p7,h7,l7);
                aph[kt][0] = packbf(h0,h1); apl[kt][0] = packbf(l0,l1);
                aph[kt][1] = packbf(h2,h3); apl[kt][1] = packbf(l2,l3);
                aph[kt][2] = packbf(h4,h5); apl[kt][2] = packbf(l4,l5);
                aph[kt][3] = packbf(h6,h7); apl[kt][3] = packbf(l6,l7);
            }
            if (kh2 == 0) {
                if (jc < 3) { CPWAIT1(); } else { CPWAIT0(); }
                __syncthreads();                  // V chunk jc ready
            }

            uint32_t koffB = (uint32_t)kh2 * 128;  // byte offset within V row

            uint32_t bvh[2][4][4];
            #pragma unroll
            for (int kt2 = 0; kt2 < 2; kt2++)
                #pragma unroll
                for (int nt = 0; nt < 4; nt++)
                    ldsm_x4(bvh[kt2][nt][0], bvh[kt2][nt][1], bvh[kt2][nt][2], bvh[kt2][nt][3],
                            sb + vbase + b_off2 + koffB + nt * 2176 + kt2 * 64);

            // term 0: PH x VH
            #pragma unroll
            for (int kt2 = 0; kt2 < 2; kt2++)
                #pragma unroll
                for (int nt = 0; nt < 4; nt++) {
                    mma16816(oacc[nt], aph[2*kt2][0], aph[2*kt2][1], aph[2*kt2][2], aph[2*kt2][3],
                             bvh[kt2][nt][0], bvh[kt2][nt][1]);
                    mma16816(oacc[nt], aph[2*kt2+1][0], aph[2*kt2+1][1], aph[2*kt2+1][2], aph[2*kt2+1][3],
                             bvh[kt2][nt][2], bvh[kt2][nt][3]);
                }
            // term 1: PH x VL (streamed)
            #pragma unroll
            for (int kt2 = 0; kt2 < 2; kt2++)
                #pragma unroll
                for (int nt = 0; nt < 4; nt++) {
                    uint32_t t0, t1, t2, t3;
                    ldsm_x4(t0, t1, t2, t3,
                            sb + vbase + 18432 + b_off2 + koffB + nt * 2176 + kt2 * 64);
                    mma16816(oacc[nt], aph[2*kt2][0], aph[2*kt2][1], aph[2*kt2][2], aph[2*kt2][3], t0, t1);
                    mma16816(oacc[nt], aph[2*kt2+1][0], aph[2*kt2+1][1], aph[2*kt2+1][2], aph[2*kt2+1][3], t2, t3);
                }
            // term 2: PL x VH
            #pragma unroll
            for (int kt2 = 0; kt2 < 2; kt2++)
                #pragma unroll
                for (int nt = 0; nt < 4; nt++) {
                    mma16816(oacc[nt], apl[2*kt2][0], apl[2*kt2][1], apl[2*kt2][2], apl[2*kt2][3],
                             bvh[kt2][nt][0], bvh[kt2][nt][1]);
                    mma16816(oacc[nt], apl[2*kt2+1][0], apl[2*kt2+1][1], apl[2*kt2+1][2], apl[2*kt2+1][3],
                             bvh[kt2][nt][2], bvh[kt2][nt][3]);
                }
        }
        __syncthreads();                          // before next V overwrite
    }

    // ---- Epilogue: RMW into out (lepe base already written) ----
    {
        int h = unit & 7;
        int sg0 = rb * 64 + mt2 * 16 + g;
        int sg1 = sg0 + 8;
        int sp0 = (sg0 >> 3) * 64 + ww * 8 + (sg0 & 7);
        int sp1 = (sg1 >> 3) * 64 + ww * 8 + (sg1 & 7);
        float* o0 = out + ((size_t)b * 4096 + sp0) * CDIM + h * HD;
        float* o1 = out + ((size_t)b * 4096 + sp1) * CDIM + h * HD;
        #pragma unroll
        for (int nt = 0; nt < 4; nt++) {
            int d0 = nb + nt * 8 + tg * 2;
            float2 c0 = *(float2*)&o0[d0];
            c0.x += oacc[nt][0]; c0.y += oacc[nt][1];
            *(float2*)&o0[d0] = c0;
            float2 c1 = *(float2*)&o1[d0];
            c1.x += oacc[nt][2]; c1.y += oacc[nt][3];
            *(float2*)&o1[d0] = c1;
        }
    }
}

// ---------------------------------------------------------------------------
extern "C" void kernel_launch(void* const* d_in, const int* in_sizes, int n_in,
                              void* d_out, int out_size) {
    const float* temp  = (const float*)d_in[0];  // [3, 8, 512, 64, 64]
    const float* polar = (const float*)d_in[1];  // [8, 64, 64, 2]
    const float* cw    = (const float*)d_in[2];  // [512, 1, 3, 3]
    const float* cb    = (const float*)d_in[3];  // [512]
    float* out = (float*)d_out;                  // [8, 4096, 512]

    const float* v = temp + 2 * PLANE_ALL;

    size_t smA = (size_t)(64 * 195 + 576 + 64) * sizeof(float);
    cudaFuncSetAttribute(lepe_kernel, cudaFuncAttributeMaxDynamicSharedMemorySize, (int)smA);
    cudaFuncSetAttribute(attn_mma_kernel, cudaFuncAttributeMaxDynamicSharedMemorySize, SMEM_ATTN);

    prep_qk<<<UNITS * 16, 256>>>(temp);
    prep_v<<<UNITS * 4, 256>>>(temp);

    dim3 gA(BATCH * 64, CDIM / 64);
    lepe_kernel<<<gA, 256, smA>>>(v, cw, cb, out);
    attn_mma_kernel<<<4096, 256, SMEM_ATTN>>>(polar, out);
}